// round 10
// baseline (speedup 1.0000x reference)
#include <cuda_runtime.h>
#include <math.h>

#define BB 4
#define SS 2048
#define HH 8
#define DK 64
#define DM 512
#define MTOT (BB*SS)   // 8192

// Scratch (allocation-free rule: __device__ globals)
__device__ float g_Q[BB*HH*SS*DK];
__device__ float g_K[BB*HH*SS*DK];
__device__ float g_V[BB*HH*SS*DK];
__device__ float g_X[BB*SS*DM];

// ---------------------------------------------------------------------------
// tf32 mma.sync.m16n8k8 (A row-major, B col-major). Lane = g*4+tg.
//   A: a0=(g,tg) a1=(g+8,tg) a2=(g,tg+4) a3=(g+8,tg+4)
//   B: b0=(k=tg,n=g) b1=(k=tg+4,n=g)
//   C: c0=(g,2tg) c1=(g,2tg+1) c2=(g+8,2tg) c3=(g+8,2tg+1)
// HMMA.tf32 ignores the low 13 mantissa bits -> raw fp32 bit patterns are
// valid tf32 operands (truncation instead of rna; ~0.5 ulp extra error).
// ---------------------------------------------------------------------------
__device__ __forceinline__ unsigned f2tf(float f) {
    unsigned u; asm("cvt.rna.tf32.f32 %0, %1;" : "=r"(u) : "f"(f)); return u;
}
__device__ __forceinline__ void mma8(float* d, const unsigned* a, const unsigned* b) {
    asm volatile("mma.sync.aligned.m16n8k8.row.col.f32.tf32.tf32.f32 "
        "{%0,%1,%2,%3},{%4,%5,%6,%7},{%8,%9},{%0,%1,%2,%3};"
        : "+f"(d[0]), "+f"(d[1]), "+f"(d[2]), "+f"(d[3])
        : "r"(a[0]), "r"(a[1]), "r"(a[2]), "r"(a[3]), "r"(b[0]), "r"(b[1]));
}
__device__ __forceinline__ void cp16(void* smem, const void* g) {
    unsigned saddr = (unsigned)__cvta_generic_to_shared(smem);
    asm volatile("cp.async.cg.shared.global [%0], [%1], 16;"
                 :: "r"(saddr), "l"(g) : "memory");
}

// ---------------------------------------------------------------------------
// GEMM: C[M,N] = A[M,512] @ W[N,512]^T + bias, tf32 tensor cores.
// Block 128(M)x64(N), 256 threads, warp tile 32x32. Register-prefetch pipeline.
// scatter=1: write to [B,H,S,DK] layout. scatter=0: row-major [M,512].
// ---------------------------------------------------------------------------
#define PA 36
__global__ __launch_bounds__(256) void gemm_tf32(
    const float* __restrict__ A, const float* __restrict__ W,
    const float* __restrict__ bias, float* __restrict__ out, int scatter)
{
    __shared__ unsigned As[128*PA];
    __shared__ unsigned Bs[64*PA];

    const int tid = threadIdx.x, lane = tid & 31, wid = tid >> 5;
    const int g = lane >> 2, tg = lane & 3;
    const int wm = (wid & 3) * 32, wn = (wid >> 2) * 32;
    const int m0 = blockIdx.y * 128, n0 = blockIdx.x * 64;

    float acc[2][4][4];
    #pragma unroll
    for (int mt = 0; mt < 2; mt++)
        #pragma unroll
        for (int nt = 0; nt < 4; nt++)
            #pragma unroll
            for (int i = 0; i < 4; i++) acc[mt][nt][i] = 0.f;

    const int ar = tid >> 1, akb = (tid & 1) * 16;
    const int br = tid >> 2, bkb = (tid & 3) * 8;
    const float* Abase = A + (size_t)(m0 + ar) * DM + akb;
    const float* Wbase = W + (size_t)(n0 + br) * DM + bkb;

    float4 pva[4], pvw[2];
    #pragma unroll
    for (int i = 0; i < 4; i++) pva[i] = *(const float4*)(Abase + i*4);
    #pragma unroll
    for (int i = 0; i < 2; i++) pvw[i] = *(const float4*)(Wbase + i*4);

    for (int k0 = 0; k0 < DM; k0 += 32) {
        #pragma unroll
        for (int i = 0; i < 4; i++) {
            float4 v = pva[i];
            *(uint4*)&As[ar*PA + akb + i*4] =
                make_uint4(f2tf(v.x), f2tf(v.y), f2tf(v.z), f2tf(v.w));
        }
        #pragma unroll
        for (int i = 0; i < 2; i++) {
            float4 v = pvw[i];
            *(uint4*)&Bs[br*PA + bkb + i*4] =
                make_uint4(f2tf(v.x), f2tf(v.y), f2tf(v.z), f2tf(v.w));
        }
        __syncthreads();

        if (k0 + 32 < DM) {     // prefetch next k-slab (overlaps MMA below)
            #pragma unroll
            for (int i = 0; i < 4; i++) pva[i] = *(const float4*)(Abase + k0+32 + i*4);
            #pragma unroll
            for (int i = 0; i < 2; i++) pvw[i] = *(const float4*)(Wbase + k0+32 + i*4);
        }

        #pragma unroll
        for (int kk = 0; kk < 32; kk += 8) {
            unsigned a[2][4], b[4][2];
            #pragma unroll
            for (int mt = 0; mt < 2; mt++) {
                int mr = wm + mt*16 + g;
                a[mt][0] = As[mr*PA + kk + tg];
                a[mt][1] = As[(mr+8)*PA + kk + tg];
                a[mt][2] = As[mr*PA + kk + tg + 4];
                a[mt][3] = As[(mr+8)*PA + kk + tg + 4];
            }
            #pragma unroll
            for (int nt = 0; nt < 4; nt++) {
                int nr = wn + nt*8 + g;
                b[nt][0] = Bs[nr*PA + kk + tg];
                b[nt][1] = Bs[nr*PA + kk + tg + 4];
            }
            #pragma unroll
            for (int mt = 0; mt < 2; mt++)
                #pragma unroll
                for (int nt = 0; nt < 4; nt++)
                    mma8(acc[mt][nt], a[mt], b[nt]);
        }
        __syncthreads();
    }

    #pragma unroll
    for (int mt = 0; mt < 2; mt++) {
        int r0 = m0 + wm + mt*16 + g;
        int r1 = r0 + 8;
        #pragma unroll
        for (int nt = 0; nt < 4; nt++) {
            int c = n0 + wn + nt*8 + tg*2;
            float2 bv = *(const float2*)(bias + c);
            float2 v0 = make_float2(acc[mt][nt][0] + bv.x, acc[mt][nt][1] + bv.y);
            float2 v1 = make_float2(acc[mt][nt][2] + bv.x, acc[mt][nt][3] + bv.y);
            if (scatter) {
                int hh = c >> 6, dd = c & 63;
                int b0 = r0 >> 11, s0 = r0 & (SS-1);
                int b1 = r1 >> 11, s1 = r1 & (SS-1);
                *(float2*)(out + (((size_t)(b0*HH + hh))*SS + s0)*DK + dd) = v0;
                *(float2*)(out + (((size_t)(b1*HH + hh))*SS + s1)*DK + dd) = v1;
            } else {
                *(float2*)(out + (size_t)r0 * DM + c) = v0;
                *(float2*)(out + (size_t)r1 * DM + c) = v1;
            }
        }
    }
}

// ---------------------------------------------------------------------------
// Flash attention, tf32, 2-stage cp.async pipeline on K/V.
// One CTA per (b, h, 128-query tile). 256 thr = 8 warps, warp grid 4(q) x 2(k/d),
// warp tile 32x32. Register-resident softmax; P spilled once for PV A-frags.
// Stage i+1 K/V load rides under stage i compute (wait_group 1).
// ---------------------------------------------------------------------------
#define QT 128
#define KT 64
#define NIT (SS/KT)   // 32
#define QSP 68   // stride (words): frag loads land on 32 distinct banks
#define VSP 72
__global__ __launch_bounds__(256) void attn_tf32(const int* __restrict__ mask,
                                                 float* __restrict__ X)
{
    extern __shared__ float smf[];
    float* Qs   = smf;                   // [128][QSP] fp32 bits (Q/8)
    float* Ks   = Qs + 128*QSP;          // [2][64][QSP] double buffer
    float* Vs   = Ks + 2*64*QSP;         // [2][64][VSP] double buffer
    float* Pm   = Vs + 2*64*VSP;         // [128][QSP] exp'd probs
    float* pmax = Pm + 128*QSP;          // [2][128]
    float* psum = pmax + 256;            // [2][128]

    const int tid = threadIdx.x, lane = tid & 31, wid = tid >> 5;
    const int g = lane >> 2, tg = lane & 3;
    const int wq = (wid & 3) * 32, wk = (wid >> 2) * 32;
    const int wki = wid >> 2;
    const int q0 = blockIdx.x * QT, h = blockIdx.y, b = blockIdx.z;
    const size_t hoff = ((size_t)(b*HH + h)) * SS * DK;

    const int kr = tid & 63, kdg = (tid >> 6) * 16;   // K/V loader mapping

    // Prologue: stage 0 K/V load in flight while Q tile is staged
    {
        const float* kp = g_K + hoff + (size_t)kr*DK + kdg;
        const float* vp = g_V + hoff + (size_t)kr*DK + kdg;
        #pragma unroll
        for (int j = 0; j < 4; j++) {
            cp16(&Ks[kr*QSP + kdg + j*4], kp + j*4);
            cp16(&Vs[kr*VSP + kdg + j*4], vp + j*4);
        }
        asm volatile("cp.async.commit_group;" ::: "memory");
    }

    // Load Q tile (scaled by 1/sqrt(64); raw fp32 bits used as tf32)
    {
        int r = tid >> 1, cb = (tid & 1) * 32;
        const float* src = g_Q + hoff + (size_t)(q0 + r)*DK + cb;
        #pragma unroll
        for (int j = 0; j < 8; j++) {
            float4 v = *(const float4*)(src + j*4);
            *(float4*)&Qs[r*QSP + cb + j*4] =
                make_float4(v.x*0.125f, v.y*0.125f, v.z*0.125f, v.w*0.125f);
        }
    }

    float o[2][4][4];
    #pragma unroll
    for (int mt = 0; mt < 2; mt++)
        #pragma unroll
        for (int nt = 0; nt < 4; nt++)
            #pragma unroll
            for (int i = 0; i < 4; i++) o[mt][nt][i] = 0.f;

    float mprev[2][2], lsum[2][2];
    #pragma unroll
    for (int mt = 0; mt < 2; mt++)
        #pragma unroll
        for (int h2 = 0; h2 < 2; h2++) { mprev[mt][h2] = -INFINITY; lsum[mt][h2] = 0.f; }

    #pragma unroll 1
    for (int it = 0; it < NIT; it++) {
        const int k0 = it * KT;
        if (it > 0) __syncthreads();      // iter it-1 fully done -> buf[(it+1)&1] free

        if (it + 1 < NIT) {               // issue stage it+1 under stage it compute
            float* Kd = Ks + ((it+1)&1)*64*QSP;
            float* Vd = Vs + ((it+1)&1)*64*VSP;
            const float* kp = g_K + hoff + (size_t)(k0 + KT + kr)*DK + kdg;
            const float* vp = g_V + hoff + (size_t)(k0 + KT + kr)*DK + kdg;
            #pragma unroll
            for (int j = 0; j < 4; j++) {
                cp16(&Kd[kr*QSP + kdg + j*4], kp + j*4);
                cp16(&Vd[kr*VSP + kdg + j*4], vp + j*4);
            }
            asm volatile("cp.async.commit_group;\ncp.async.wait_group 1;" ::: "memory");
        } else {
            asm volatile("cp.async.wait_group 0;" ::: "memory");
        }
        __syncthreads();                  // stage it visible to all warps

        const float* Kc = Ks + (it&1)*64*QSP;
        const float* Vc = Vs + (it&1)*64*VSP;

        // ---- mask prefetch (LDG latency hides under QK MMAs below) ----
        int2 mreg[2][2][4];
        #pragma unroll
        for (int mt = 0; mt < 2; mt++)
            #pragma unroll
            for (int h2 = 0; h2 < 2; h2++) {
                int row = q0 + wq + mt*16 + h2*8 + g;
                const int* mp = mask + ((size_t)b*SS + row)*SS + k0 + wk;
                #pragma unroll
                for (int nt = 0; nt < 4; nt++)
                    mreg[mt][h2][nt] = *(const int2*)(mp + nt*8 + tg*2);
            }

        // ---- S = (Q/8) @ K^T : 32x64 per warp-row covered by warp pair ----
        float s[2][4][4];
        #pragma unroll
        for (int mt = 0; mt < 2; mt++)
            #pragma unroll
            for (int nt = 0; nt < 4; nt++)
                #pragma unroll
                for (int i = 0; i < 4; i++) s[mt][nt][i] = 0.f;

        #pragma unroll
        for (int kk = 0; kk < 64; kk += 8) {
            unsigned a[2][4], bb[4][2];
            #pragma unroll
            for (int mt = 0; mt < 2; mt++) {
                int r = wq + mt*16 + g;
                a[mt][0] = __float_as_uint(Qs[r*QSP + kk + tg]);
                a[mt][1] = __float_as_uint(Qs[(r+8)*QSP + kk + tg]);
                a[mt][2] = __float_as_uint(Qs[r*QSP + kk + tg + 4]);
                a[mt][3] = __float_as_uint(Qs[(r+8)*QSP + kk + tg + 4]);
            }
            #pragma unroll
            for (int nt = 0; nt < 4; nt++) {
                int c = wk + nt*8 + g;
                bb[nt][0] = __float_as_uint(Kc[c*QSP + kk + tg]);
                bb[nt][1] = __float_as_uint(Kc[c*QSP + kk + tg + 4]);
            }
            #pragma unroll
            for (int mt = 0; mt < 2; mt++)
                #pragma unroll
                for (int nt = 0; nt < 4; nt++)
                    mma8(s[mt][nt], a[mt], bb[nt]);
        }

        // ---- apply mask from registers ----
        #pragma unroll
        for (int mt = 0; mt < 2; mt++)
            #pragma unroll
            for (int h2 = 0; h2 < 2; h2++)
                #pragma unroll
                for (int nt = 0; nt < 4; nt++) {
                    if (mreg[mt][h2][nt].x == 0) s[mt][nt][h2*2]   = -1e9f;
                    if (mreg[mt][h2][nt].y == 0) s[mt][nt][h2*2+1] = -1e9f;
                }

        // ---- per-row max (in-register + shfl + cross-warp exchange) ----
        #pragma unroll
        for (int mt = 0; mt < 2; mt++)
            #pragma unroll
            for (int h2 = 0; h2 < 2; h2++) {
                float m = fmaxf(s[mt][0][h2*2], s[mt][0][h2*2+1]);
                #pragma unroll
                for (int nt = 1; nt < 4; nt++)
                    m = fmaxf(m, fmaxf(s[mt][nt][h2*2], s[mt][nt][h2*2+1]));
                m = fmaxf(m, __shfl_xor_sync(0xffffffffu, m, 1));
                m = fmaxf(m, __shfl_xor_sync(0xffffffffu, m, 2));
                if (tg == 0) pmax[wki*128 + wq + mt*16 + h2*8 + g] = m;
            }
        __syncthreads();

        // ---- combine max, exp in registers, partial sums, spill P ----
        float fr[2][2];
        #pragma unroll
        for (int mt = 0; mt < 2; mt++)
            #pragma unroll
            for (int h2 = 0; h2 < 2; h2++) {
                int row = wq + mt*16 + h2*8 + g;
                float mn = fmaxf(pmax[row], pmax[128 + row]);
                mn = fmaxf(mprev[mt][h2], mn);
                fr[mt][h2] = __expf(mprev[mt][h2] - mn);   // exp(-inf)=0 first iter
                mprev[mt][h2] = mn;
                float ssum = 0.f;
                #pragma unroll
                for (int nt = 0; nt < 4; nt++) {
                    float p0 = __expf(s[mt][nt][h2*2]   - mn);
                    float p1 = __expf(s[mt][nt][h2*2+1] - mn);
                    s[mt][nt][h2*2] = p0; s[mt][nt][h2*2+1] = p1;
                    ssum += p0 + p1;
                }
                ssum += __shfl_xor_sync(0xffffffffu, ssum, 1);
                ssum += __shfl_xor_sync(0xffffffffu, ssum, 2);
                if (tg == 0) psum[wki*128 + row] = ssum;
            }
        #pragma unroll
        for (int mt = 0; mt < 2; mt++)
            #pragma unroll
            for (int h2 = 0; h2 < 2; h2++) {
                int r = wq + mt*16 + h2*8 + g;
                #pragma unroll
                for (int nt = 0; nt < 4; nt++)
                    *(float2*)&Pm[r*QSP + wk + nt*8 + tg*2] =
                        make_float2(s[mt][nt][h2*2], s[mt][nt][h2*2+1]);
            }
        __syncthreads();

        // ---- update l, rescale O, O += P @ V ----
        #pragma unroll
        for (int mt = 0; mt < 2; mt++)
            #pragma unroll
            for (int h2 = 0; h2 < 2; h2++) {
                int row = wq + mt*16 + h2*8 + g;
                lsum[mt][h2] = lsum[mt][h2]*fr[mt][h2] + psum[row] + psum[128 + row];
            }
        #pragma unroll
        for (int mt = 0; mt < 2; mt++)
            #pragma unroll
            for (int nt = 0; nt < 4; nt++) {
                o[mt][nt][0] *= fr[mt][0]; o[mt][nt][1] *= fr[mt][0];
                o[mt][nt][2] *= fr[mt][1]; o[mt][nt][3] *= fr[mt][1];
            }
        #pragma unroll
        for (int kk = 0; kk < 64; kk += 8) {
            unsigned a[2][4], bb[4][2];
            #pragma unroll
            for (int mt = 0; mt < 2; mt++) {
                int r = wq + mt*16 + g;
                a[mt][0] = __float_as_uint(Pm[r*QSP + kk + tg]);
                a[mt][1] = __float_as_uint(Pm[(r+8)*QSP + kk + tg]);
                a[mt][2] = __float_as_uint(Pm[r*QSP + kk + tg + 4]);
                a[mt][3] = __float_as_uint(Pm[(r+8)*QSP + kk + tg + 4]);
            }
            #pragma unroll
            for (int nt = 0; nt < 4; nt++) {
                int c = wk + nt*8 + g;   // d-column for this warp
                bb[nt][0] = __float_as_uint(Vc[(kk+tg)*VSP + c]);
                bb[nt][1] = __float_as_uint(Vc[(kk+tg+4)*VSP + c]);
            }
            #pragma unroll
            for (int mt = 0; mt < 2; mt++)
                #pragma unroll
                for (int nt = 0; nt < 4; nt++)
                    mma8(o[mt][nt], a[mt], bb[nt]);
        }
    }

    // ---- normalize, write X in [B,S,DM] (head-merged for Wo GEMM) ----
    #pragma unroll
    for (int mt = 0; mt < 2; mt++)
        #pragma unroll
        for (int h2 = 0; h2 < 2; h2++) {
            int r = q0 + wq + mt*16 + h2*8 + g;
            float inv = 1.f / lsum[mt][h2];
            float* xp = X + ((size_t)b*SS + r)*DM + h*DK + wk;
            #pragma unroll
            for (int nt = 0; nt < 4; nt++)
                *(float2*)(xp + nt*8 + tg*2) =
                    make_float2(o[mt][nt][h2*2]*inv, o[mt][nt][h2*2+1]*inv);
        }
}

// ---------------------------------------------------------------------------
extern "C" void kernel_launch(void* const* d_in, const int* in_sizes, int n_in,
                              void* d_out, int out_size)
{
    const float* query = (const float*)d_in[0];
    const float* key   = (const float*)d_in[1];
    const float* value = (const float*)d_in[2];
    const int*   mask  = (const int*)  d_in[3];
    const float* Wq = (const float*)d_in[4];
    const float* bq = (const float*)d_in[5];
    const float* Wk = (const float*)d_in[6];
    const float* bk = (const float*)d_in[7];
    const float* Wv = (const float*)d_in[8];
    const float* bv = (const float*)d_in[9];
    const float* Wo = (const float*)d_in[10];
    const float* bo = (const float*)d_in[11];
    float* out = (float*)d_out;

    void *qp, *kp, *vp, *xp;
    cudaGetSymbolAddress(&qp, g_Q);
    cudaGetSymbolAddress(&kp, g_K);
    cudaGetSymbolAddress(&vp, g_V);
    cudaGetSymbolAddress(&xp, g_X);

    dim3 gg(DM/64, MTOT/128);   // (8, 64)
    gemm_tf32<<<gg, 256>>>(query, Wq, bq, (float*)qp, 1);
    gemm_tf32<<<gg, 256>>>(key,   Wk, bk, (float*)kp, 1);
    gemm_tf32<<<gg, 256>>>(value, Wv, bv, (float*)vp, 1);

    const int smem = (128*QSP + 2*64*QSP + 2*64*VSP + 128*QSP + 512) * (int)sizeof(float);
    cudaFuncSetAttribute(attn_tf32, cudaFuncAttributeMaxDynamicSharedMemorySize, smem);
    dim3 ag(SS/QT, HH, BB);     // (16, 8, 4)
    attn_tf32<<<ag, 256, smem>>>(mask, (float*)xp);

    gemm_tf32<<<gg, 256>>>((const float*)xp, Wo, bo, out, 0);
}

// round 13
// speedup vs baseline: 1.1689x; 1.1689x over previous
#include <cuda_runtime.h>
#include <math.h>

#define BB 4
#define SS 2048
#define HH 8
#define DK 64
#define DM 512
#define MTOT (BB*SS)   // 8192

// Scratch (allocation-free rule: __device__ globals)
__device__ float g_Q[BB*HH*SS*DK];
__device__ float g_K[BB*HH*SS*DK];
__device__ float g_V[BB*HH*SS*DK];
__device__ float g_X[BB*SS*DM];

// ---------------------------------------------------------------------------
// tf32 mma.sync.m16n8k8 (A row-major, B col-major). Lane = g*4+tg.
//   A: a0=(g,tg) a1=(g+8,tg) a2=(g,tg+4) a3=(g+8,tg+4)
//   B: b0=(k=tg,n=g) b1=(k=tg+4,n=g)
//   C: c0=(g,2tg) c1=(g,2tg+1) c2=(g+8,2tg) c3=(g+8,2tg+1)
// HMMA.tf32 ignores the low 13 mantissa bits -> raw fp32 bits are valid
// tf32 operands (truncation instead of rna).
// ---------------------------------------------------------------------------
__device__ __forceinline__ unsigned f2tf(float f) {
    unsigned u; asm("cvt.rna.tf32.f32 %0, %1;" : "=r"(u) : "f"(f)); return u;
}
__device__ __forceinline__ void mma8(float* d, const unsigned* a, const unsigned* b) {
    asm volatile("mma.sync.aligned.m16n8k8.row.col.f32.tf32.tf32.f32 "
        "{%0,%1,%2,%3},{%4,%5,%6,%7},{%8,%9},{%0,%1,%2,%3};"
        : "+f"(d[0]), "+f"(d[1]), "+f"(d[2]), "+f"(d[3])
        : "r"(a[0]), "r"(a[1]), "r"(a[2]), "r"(a[3]), "r"(b[0]), "r"(b[1]));
}
__device__ __forceinline__ void cp16(void* smem, const void* g) {
    unsigned saddr = (unsigned)__cvta_generic_to_shared(smem);
    asm volatile("cp.async.cg.shared.global [%0], [%1], 16;"
                 :: "r"(saddr), "l"(g) : "memory");
}

// ---------------------------------------------------------------------------
// GEMM: C[M,N] = A[M,512] @ W[N,512]^T + bias, tf32 tensor cores.
// Block 128(M)x64(N), 256 threads, warp tile 32x32. Register-prefetch pipeline.
// scatter=1: write to [B,H,S,DK] layout. scatter=0: row-major [M,512].
// ---------------------------------------------------------------------------
#define PA 36
__global__ __launch_bounds__(256) void gemm_tf32(
    const float* __restrict__ A, const float* __restrict__ W,
    const float* __restrict__ bias, float* __restrict__ out, int scatter)
{
    __shared__ unsigned As[128*PA];
    __shared__ unsigned Bs[64*PA];

    const int tid = threadIdx.x, lane = tid & 31, wid = tid >> 5;
    const int g = lane >> 2, tg = lane & 3;
    const int wm = (wid & 3) * 32, wn = (wid >> 2) * 32;
    const int m0 = blockIdx.y * 128, n0 = blockIdx.x * 64;

    float acc[2][4][4];
    #pragma unroll
    for (int mt = 0; mt < 2; mt++)
        #pragma unroll
        for (int nt = 0; nt < 4; nt++)
            #pragma unroll
            for (int i = 0; i < 4; i++) acc[mt][nt][i] = 0.f;

    const int ar = tid >> 1, akb = (tid & 1) * 16;
    const int br = tid >> 2, bkb = (tid & 3) * 8;
    const float* Abase = A + (size_t)(m0 + ar) * DM + akb;
    const float* Wbase = W + (size_t)(n0 + br) * DM + bkb;

    float4 pva[4], pvw[2];
    #pragma unroll
    for (int i = 0; i < 4; i++) pva[i] = *(const float4*)(Abase + i*4);
    #pragma unroll
    for (int i = 0; i < 2; i++) pvw[i] = *(const float4*)(Wbase + i*4);

    for (int k0 = 0; k0 < DM; k0 += 32) {
        #pragma unroll
        for (int i = 0; i < 4; i++) {
            float4 v = pva[i];
            *(uint4*)&As[ar*PA + akb + i*4] =
                make_uint4(f2tf(v.x), f2tf(v.y), f2tf(v.z), f2tf(v.w));
        }
        #pragma unroll
        for (int i = 0; i < 2; i++) {
            float4 v = pvw[i];
            *(uint4*)&Bs[br*PA + bkb + i*4] =
                make_uint4(f2tf(v.x), f2tf(v.y), f2tf(v.z), f2tf(v.w));
        }
        __syncthreads();

        if (k0 + 32 < DM) {     // prefetch next k-slab (overlaps MMA below)
            #pragma unroll
            for (int i = 0; i < 4; i++) pva[i] = *(const float4*)(Abase + k0+32 + i*4);
            #pragma unroll
            for (int i = 0; i < 2; i++) pvw[i] = *(const float4*)(Wbase + k0+32 + i*4);
        }

        #pragma unroll
        for (int kk = 0; kk < 32; kk += 8) {
            unsigned a[2][4], b[4][2];
            #pragma unroll
            for (int mt = 0; mt < 2; mt++) {
                int mr = wm + mt*16 + g;
                a[mt][0] = As[mr*PA + kk + tg];
                a[mt][1] = As[(mr+8)*PA + kk + tg];
                a[mt][2] = As[mr*PA + kk + tg + 4];
                a[mt][3] = As[(mr+8)*PA + kk + tg + 4];
            }
            #pragma unroll
            for (int nt = 0; nt < 4; nt++) {
                int nr = wn + nt*8 + g;
                b[nt][0] = Bs[nr*PA + kk + tg];
                b[nt][1] = Bs[nr*PA + kk + tg + 4];
            }
            #pragma unroll
            for (int mt = 0; mt < 2; mt++)
                #pragma unroll
                for (int nt = 0; nt < 4; nt++)
                    mma8(acc[mt][nt], a[mt], b[nt]);
        }
        __syncthreads();
    }

    #pragma unroll
    for (int mt = 0; mt < 2; mt++) {
        int r0 = m0 + wm + mt*16 + g;
        int r1 = r0 + 8;
        #pragma unroll
        for (int nt = 0; nt < 4; nt++) {
            int c = n0 + wn + nt*8 + tg*2;
            float2 bv = *(const float2*)(bias + c);
            float2 v0 = make_float2(acc[mt][nt][0] + bv.x, acc[mt][nt][1] + bv.y);
            float2 v1 = make_float2(acc[mt][nt][2] + bv.x, acc[mt][nt][3] + bv.y);
            if (scatter) {
                int hh = c >> 6, dd = c & 63;
                int b0 = r0 >> 11, s0 = r0 & (SS-1);
                int b1 = r1 >> 11, s1 = r1 & (SS-1);
                *(float2*)(out + (((size_t)(b0*HH + hh))*SS + s0)*DK + dd) = v0;
                *(float2*)(out + (((size_t)(b1*HH + hh))*SS + s1)*DK + dd) = v1;
            } else {
                *(float2*)(out + (size_t)r0 * DM + c) = v0;
                *(float2*)(out + (size_t)r1 * DM + c) = v1;
            }
        }
    }
}

// ---------------------------------------------------------------------------
// Flash attention, tf32. One CTA per (b, h, 128-query tile). 256 thr = 8 warps.
// Warp tile 16(q) x 64(k): softmax fully warp-local (no cross-warp exchange,
// 2 barriers/iter). Single-buffer K/V with staggered cp.async:
//   V[it] issued at sync#1 (hides under mask LDG + QK),
//   K[it+1] issued at sync#2 (hides under softmax + PV).
// ---------------------------------------------------------------------------
#define QT 128
#define KT 64
#define NIT (SS/KT)   // 32
#define QSP 68   // stride (words): (4g+tg) frag pattern -> 32 distinct banks
#define VSP 72   // (8tg+g) pattern -> 32 distinct banks
__global__ __launch_bounds__(256, 2) void attn_tf32(const int* __restrict__ mask,
                                                    float* __restrict__ X)
{
    extern __shared__ float smf[];
    float* Qs = smf;               // [128][QSP] fp32 bits (Q/8)
    float* Ks = Qs + 128*QSP;      // [64][QSP]
    float* Vs = Ks + 64*QSP;       // [64][VSP]
    float* Pm = Vs + 64*VSP;       // [128][QSP] exp'd probs (per-warp private rows)

    const int tid = threadIdx.x, lane = tid & 31, wid = tid >> 5;
    const int g = lane >> 2, tg = lane & 3;
    const int wq = wid * 16;                   // warp's 16 q-rows
    const int q0 = blockIdx.x * QT, h = blockIdx.y, b = blockIdx.z;
    const size_t hoff = ((size_t)(b*HH + h)) * SS * DK;

    const int kr = tid & 63, kdg = (tid >> 6) * 16;   // K/V loader mapping

    // Prologue: K0 in flight while Q tile is staged
    {
        const float* kp = g_K + hoff + (size_t)kr*DK + kdg;
        #pragma unroll
        for (int j = 0; j < 4; j++) cp16(&Ks[kr*QSP + kdg + j*4], kp + j*4);
        asm volatile("cp.async.commit_group;" ::: "memory");
    }
    {
        int r = tid >> 1, cb = (tid & 1) * 32;
        const float* src = g_Q + hoff + (size_t)(q0 + r)*DK + cb;
        #pragma unroll
        for (int j = 0; j < 8; j++) {
            float4 v = *(const float4*)(src + j*4);
            *(float4*)&Qs[r*QSP + cb + j*4] =
                make_float4(v.x*0.125f, v.y*0.125f, v.z*0.125f, v.w*0.125f);
        }
    }

    float o[8][4];
    #pragma unroll
    for (int nt = 0; nt < 8; nt++)
        #pragma unroll
        for (int i = 0; i < 4; i++) o[nt][i] = 0.f;
    float mprev0 = -INFINITY, mprev1 = -INFINITY, lsum0 = 0.f, lsum1 = 0.f;

    #pragma unroll 1
    for (int it = 0; it < NIT; it++) {
        const int k0 = it * KT;

        asm volatile("cp.async.wait_group 0;" ::: "memory");  // K[it] arrived
        __syncthreads();   // sync#1: K visible; PV(it-1) done by all -> Vs free

        // issue V[it] (rides under mask LDG + QK)
        {
            const float* vp = g_V + hoff + (size_t)(k0 + kr)*DK + kdg;
            #pragma unroll
            for (int j = 0; j < 4; j++) cp16(&Vs[kr*VSP + kdg + j*4], vp + j*4);
            asm volatile("cp.async.commit_group;" ::: "memory");
        }

        // mask prefetch (LDG latency hides under QK MMAs)
        int2 mr0[8], mr1[8];
        {
            const int* mp0 = mask + ((size_t)b*SS + (q0 + wq + g))*SS + k0;
            const int* mp1 = mp0 + 8*SS;
            #pragma unroll
            for (int nt = 0; nt < 8; nt++) {
                mr0[nt] = *(const int2*)(mp0 + nt*8 + tg*2);
                mr1[nt] = *(const int2*)(mp1 + nt*8 + tg*2);
            }
        }

        // ---- S = (Q/8) @ K^T : 16x64 per warp ----
        float s[8][4];
        #pragma unroll
        for (int nt = 0; nt < 8; nt++)
            #pragma unroll
            for (int i = 0; i < 4; i++) s[nt][i] = 0.f;
        #pragma unroll
        for (int kk = 0; kk < 64; kk += 8) {
            unsigned a[4], bb[8][2];
            a[0] = __float_as_uint(Qs[(wq+g)*QSP + kk + tg]);
            a[1] = __float_as_uint(Qs[(wq+g+8)*QSP + kk + tg]);
            a[2] = __float_as_uint(Qs[(wq+g)*QSP + kk + tg + 4]);
            a[3] = __float_as_uint(Qs[(wq+g+8)*QSP + kk + tg + 4]);
            #pragma unroll
            for (int nt = 0; nt < 8; nt++) {
                bb[nt][0] = __float_as_uint(Ks[(nt*8+g)*QSP + kk + tg]);
                bb[nt][1] = __float_as_uint(Ks[(nt*8+g)*QSP + kk + tg + 4]);
            }
            #pragma unroll
            for (int nt = 0; nt < 8; nt++) mma8(s[nt], a, bb[nt]);
        }

        // ---- apply mask ----
        #pragma unroll
        for (int nt = 0; nt < 8; nt++) {
            if (mr0[nt].x == 0) s[nt][0] = -1e9f;
            if (mr0[nt].y == 0) s[nt][1] = -1e9f;
            if (mr1[nt].x == 0) s[nt][2] = -1e9f;
            if (mr1[nt].y == 0) s[nt][3] = -1e9f;
        }

        asm volatile("cp.async.wait_group 0;" ::: "memory");  // V[it] arrived
        __syncthreads();   // sync#2: V visible; QK done by all -> Ks free

        // issue K[it+1] (rides under softmax + PV)
        if (it + 1 < NIT) {
            const float* kp = g_K + hoff + (size_t)(k0 + KT + kr)*DK + kdg;
            #pragma unroll
            for (int j = 0; j < 4; j++) cp16(&Ks[kr*QSP + kdg + j*4], kp + j*4);
            asm volatile("cp.async.commit_group;" ::: "memory");
        }

        // ---- warp-local online softmax (rows g and g+8 of warp band) ----
        float fr0, fr1;
        {
            float mx0 = fmaxf(s[0][0], s[0][1]), mx1 = fmaxf(s[0][2], s[0][3]);
            #pragma unroll
            for (int nt = 1; nt < 8; nt++) {
                mx0 = fmaxf(mx0, fmaxf(s[nt][0], s[nt][1]));
                mx1 = fmaxf(mx1, fmaxf(s[nt][2], s[nt][3]));
            }
            mx0 = fmaxf(mx0, __shfl_xor_sync(0xffffffffu, mx0, 1));
            mx0 = fmaxf(mx0, __shfl_xor_sync(0xffffffffu, mx0, 2));
            mx1 = fmaxf(mx1, __shfl_xor_sync(0xffffffffu, mx1, 1));
            mx1 = fmaxf(mx1, __shfl_xor_sync(0xffffffffu, mx1, 2));
            float mn0 = fmaxf(mprev0, mx0), mn1 = fmaxf(mprev1, mx1);
            fr0 = __expf(mprev0 - mn0); fr1 = __expf(mprev1 - mn1);
            mprev0 = mn0; mprev1 = mn1;
            float ps0 = 0.f, ps1 = 0.f;
            #pragma unroll
            for (int nt = 0; nt < 8; nt++) {
                float p0 = __expf(s[nt][0] - mn0), p1 = __expf(s[nt][1] - mn0);
                float p2 = __expf(s[nt][2] - mn1), p3 = __expf(s[nt][3] - mn1);
                s[nt][0] = p0; s[nt][1] = p1; s[nt][2] = p2; s[nt][3] = p3;
                ps0 += p0 + p1; ps1 += p2 + p3;
            }
            ps0 += __shfl_xor_sync(0xffffffffu, ps0, 1);
            ps0 += __shfl_xor_sync(0xffffffffu, ps0, 2);
            ps1 += __shfl_xor_sync(0xffffffffu, ps1, 1);
            ps1 += __shfl_xor_sync(0xffffffffu, ps1, 2);
            lsum0 = lsum0*fr0 + ps0;
            lsum1 = lsum1*fr1 + ps1;
        }

        // ---- spill P (warp-private rows; no CTA barrier needed) ----
        #pragma unroll
        for (int nt = 0; nt < 8; nt++) {
            *(float2*)&Pm[(wq+g)*QSP + nt*8 + tg*2]   = make_float2(s[nt][0], s[nt][1]);
            *(float2*)&Pm[(wq+g+8)*QSP + nt*8 + tg*2] = make_float2(s[nt][2], s[nt][3]);
        }
        __syncwarp();

        // ---- rescale O, O += P @ V ----
        #pragma unroll
        for (int nt = 0; nt < 8; nt++) {
            o[nt][0] *= fr0; o[nt][1] *= fr0;
            o[nt][2] *= fr1; o[nt][3] *= fr1;
        }
        #pragma unroll
        for (int kk = 0; kk < 64; kk += 8) {
            unsigned a[4], bb[8][2];
            a[0] = __float_as_uint(Pm[(wq+g)*QSP + kk + tg]);
            a[1] = __float_as_uint(Pm[(wq+g+8)*QSP + kk + tg]);
            a[2] = __float_as_uint(Pm[(wq+g)*QSP + kk + tg + 4]);
            a[3] = __float_as_uint(Pm[(wq+g+8)*QSP + kk + tg + 4]);
            #pragma unroll
            for (int nt = 0; nt < 8; nt++) {
                bb[nt][0] = __float_as_uint(Vs[(kk+tg)*VSP + nt*8 + g]);
                bb[nt][1] = __float_as_uint(Vs[(kk+tg+4)*VSP + nt*8 + g]);
            }
            #pragma unroll
            for (int nt = 0; nt < 8; nt++) mma8(o[nt], a, bb[nt]);
        }
    }

    // ---- normalize, write X in [B,S,DM] (head-merged for Wo GEMM) ----
    {
        float i0 = 1.f / lsum0, i1 = 1.f / lsum1;
        float* x0 = X + ((size_t)b*SS + q0 + wq + g)*DM + h*DK;
        float* x1 = X + ((size_t)b*SS + q0 + wq + g + 8)*DM + h*DK;
        #pragma unroll
        for (int nt = 0; nt < 8; nt++) {
            *(float2*)(x0 + nt*8 + tg*2) = make_float2(o[nt][0]*i0, o[nt][1]*i0);
            *(float2*)(x1 + nt*8 + tg*2) = make_float2(o[nt][2]*i1, o[nt][3]*i1);
        }
    }
}

// ---------------------------------------------------------------------------
extern "C" void kernel_launch(void* const* d_in, const int* in_sizes, int n_in,
                              void* d_out, int out_size)
{
    const float* query = (const float*)d_in[0];
    const float* key   = (const float*)d_in[1];
    const float* value = (const float*)d_in[2];
    const int*   mask  = (const int*)  d_in[3];
    const float* Wq = (const float*)d_in[4];
    const float* bq = (const float*)d_in[5];
    const float* Wk = (const float*)d_in[6];
    const float* bk = (const float*)d_in[7];
    const float* Wv = (const float*)d_in[8];
    const float* bv = (const float*)d_in[9];
    const float* Wo = (const float*)d_in[10];
    const float* bo = (const float*)d_in[11];
    float* out = (float*)d_out;

    void *qp, *kp, *vp, *xp;
    cudaGetSymbolAddress(&qp, g_Q);
    cudaGetSymbolAddress(&kp, g_K);
    cudaGetSymbolAddress(&vp, g_V);
    cudaGetSymbolAddress(&xp, g_X);

    dim3 gg(DM/64, MTOT/128);   // (8, 64)
    gemm_tf32<<<gg, 256>>>(query, Wq, bq, (float*)qp, 1);
    gemm_tf32<<<gg, 256>>>(key,   Wk, bk, (float*)kp, 1);
    gemm_tf32<<<gg, 256>>>(value, Wv, bv, (float*)vp, 1);

    const int smem = (128*QSP + 64*QSP + 64*VSP + 128*QSP) * (int)sizeof(float); // ~103KB
    cudaFuncSetAttribute(attn_tf32, cudaFuncAttributeMaxDynamicSharedMemorySize, smem);
    dim3 ag(SS/QT, HH, BB);     // (16, 8, 4)
    attn_tf32<<<ag, 256, smem>>>(mask, (float*)xp);

    gemm_tf32<<<gg, 256>>>((const float*)xp, Wo, bo, out, 0);
}

// round 14
// speedup vs baseline: 1.7653x; 1.5102x over previous
#include <cuda_runtime.h>
#include <cuda_fp16.h>
#include <math.h>

#define BB 4
#define SS 2048
#define HH 8
#define DK 64
#define DM 512
#define MTOT (BB*SS)   // 8192

// Scratch (allocation-free rule: __device__ globals). Q/K/V as fp16 (Q pre-scaled).
__device__ __half g_Q[BB*HH*SS*DK];
__device__ __half g_K[BB*HH*SS*DK];
__device__ __half g_V[BB*HH*SS*DK];
__device__ float  g_X[BB*SS*DM];

// ---------------------------------------------------------------------------
// Helpers. Lane = g*4+tg (g=lane>>2, tg=lane&3).
// tf32 m16n8k8 used in projection GEMMs (operands from fp32 weights).
// fp16 m16n8k16 used in attention (same 10-bit mantissa as tf32).
// ---------------------------------------------------------------------------
__device__ __forceinline__ unsigned f2tf(float f) {
    unsigned u; asm("cvt.rna.tf32.f32 %0, %1;" : "=r"(u) : "f"(f)); return u;
}
__device__ __forceinline__ void mma8(float* d, const unsigned* a, const unsigned* b) {
    asm volatile("mma.sync.aligned.m16n8k8.row.col.f32.tf32.tf32.f32 "
        "{%0,%1,%2,%3},{%4,%5,%6,%7},{%8,%9},{%0,%1,%2,%3};"
        : "+f"(d[0]), "+f"(d[1]), "+f"(d[2]), "+f"(d[3])
        : "r"(a[0]), "r"(a[1]), "r"(a[2]), "r"(a[3]), "r"(b[0]), "r"(b[1]));
}
__device__ __forceinline__ void mma16(float* d, const unsigned* a, const unsigned* b) {
    asm volatile("mma.sync.aligned.m16n8k16.row.col.f32.f16.f16.f32 "
        "{%0,%1,%2,%3},{%4,%5,%6,%7},{%8,%9},{%0,%1,%2,%3};"
        : "+f"(d[0]), "+f"(d[1]), "+f"(d[2]), "+f"(d[3])
        : "r"(a[0]), "r"(a[1]), "r"(a[2]), "r"(a[3]), "r"(b[0]), "r"(b[1]));
}
__device__ __forceinline__ void ldsm4(unsigned* r, unsigned addr) {
    asm volatile("ldmatrix.sync.aligned.m8n8.x4.shared.b16 {%0,%1,%2,%3}, [%4];"
        : "=r"(r[0]), "=r"(r[1]), "=r"(r[2]), "=r"(r[3]) : "r"(addr));
}
__device__ __forceinline__ void ldsm4t(unsigned* r, unsigned addr) {
    asm volatile("ldmatrix.sync.aligned.m8n8.x4.trans.shared.b16 {%0,%1,%2,%3}, [%4];"
        : "=r"(r[0]), "=r"(r[1]), "=r"(r[2]), "=r"(r[3]) : "r"(addr));
}
__device__ __forceinline__ void cp16(void* smem, const void* g) {
    unsigned saddr = (unsigned)__cvta_generic_to_shared(smem);
    asm volatile("cp.async.cg.shared.global [%0], [%1], 16;"
                 :: "r"(saddr), "l"(g) : "memory");
}

// ---------------------------------------------------------------------------
// GEMM: C[M,N] = A[M,512] @ W[N,512]^T + bias, tf32 compute.
// scatter=1: write __half to [B,H,S,DK] layout, scaled by oscale.
// scatter=0: write float row-major [M,512].
// ---------------------------------------------------------------------------
#define PA 36
__global__ __launch_bounds__(256) void gemm_tf32(
    const float* __restrict__ A, const float* __restrict__ W,
    const float* __restrict__ bias, void* __restrict__ out, int scatter, float oscale)
{
    __shared__ unsigned As[128*PA];
    __shared__ unsigned Bs[64*PA];

    const int tid = threadIdx.x, lane = tid & 31, wid = tid >> 5;
    const int g = lane >> 2, tg = lane & 3;
    const int wm = (wid & 3) * 32, wn = (wid >> 2) * 32;
    const int m0 = blockIdx.y * 128, n0 = blockIdx.x * 64;

    float acc[2][4][4];
    #pragma unroll
    for (int mt = 0; mt < 2; mt++)
        #pragma unroll
        for (int nt = 0; nt < 4; nt++)
            #pragma unroll
            for (int i = 0; i < 4; i++) acc[mt][nt][i] = 0.f;

    const int ar = tid >> 1, akb = (tid & 1) * 16;
    const int br = tid >> 2, bkb = (tid & 3) * 8;
    const float* Abase = A + (size_t)(m0 + ar) * DM + akb;
    const float* Wbase = W + (size_t)(n0 + br) * DM + bkb;

    float4 pva[4], pvw[2];
    #pragma unroll
    for (int i = 0; i < 4; i++) pva[i] = *(const float4*)(Abase + i*4);
    #pragma unroll
    for (int i = 0; i < 2; i++) pvw[i] = *(const float4*)(Wbase + i*4);

    for (int k0 = 0; k0 < DM; k0 += 32) {
        #pragma unroll
        for (int i = 0; i < 4; i++) {
            float4 v = pva[i];
            *(uint4*)&As[ar*PA + akb + i*4] =
                make_uint4(f2tf(v.x), f2tf(v.y), f2tf(v.z), f2tf(v.w));
        }
        #pragma unroll
        for (int i = 0; i < 2; i++) {
            float4 v = pvw[i];
            *(uint4*)&Bs[br*PA + bkb + i*4] =
                make_uint4(f2tf(v.x), f2tf(v.y), f2tf(v.z), f2tf(v.w));
        }
        __syncthreads();

        if (k0 + 32 < DM) {
            #pragma unroll
            for (int i = 0; i < 4; i++) pva[i] = *(const float4*)(Abase + k0+32 + i*4);
            #pragma unroll
            for (int i = 0; i < 2; i++) pvw[i] = *(const float4*)(Wbase + k0+32 + i*4);
        }

        #pragma unroll
        for (int kk = 0; kk < 32; kk += 8) {
            unsigned a[2][4], b[4][2];
            #pragma unroll
            for (int mt = 0; mt < 2; mt++) {
                int mr = wm + mt*16 + g;
                a[mt][0] = As[mr*PA + kk + tg];
                a[mt][1] = As[(mr+8)*PA + kk + tg];
                a[mt][2] = As[mr*PA + kk + tg + 4];
                a[mt][3] = As[(mr+8)*PA + kk + tg + 4];
            }
            #pragma unroll
            for (int nt = 0; nt < 4; nt++) {
                int nr = wn + nt*8 + g;
                b[nt][0] = Bs[nr*PA + kk + tg];
                b[nt][1] = Bs[nr*PA + kk + tg + 4];
            }
            #pragma unroll
            for (int mt = 0; mt < 2; mt++)
                #pragma unroll
                for (int nt = 0; nt < 4; nt++)
                    mma8(acc[mt][nt], a[mt], b[nt]);
        }
        __syncthreads();
    }

    #pragma unroll
    for (int mt = 0; mt < 2; mt++) {
        int r0 = m0 + wm + mt*16 + g;
        int r1 = r0 + 8;
        #pragma unroll
        for (int nt = 0; nt < 4; nt++) {
            int c = n0 + wn + nt*8 + tg*2;
            float2 bv = *(const float2*)(bias + c);
            float v00 = acc[mt][nt][0] + bv.x, v01 = acc[mt][nt][1] + bv.y;
            float v10 = acc[mt][nt][2] + bv.x, v11 = acc[mt][nt][3] + bv.y;
            if (scatter) {
                __half* oh = (__half*)out;
                int hh = c >> 6, dd = c & 63;
                int b0 = r0 >> 11, s0 = r0 & (SS-1);
                int b1 = r1 >> 11, s1 = r1 & (SS-1);
                *(__half2*)(oh + (((size_t)(b0*HH + hh))*SS + s0)*DK + dd) =
                    __floats2half2_rn(v00*oscale, v01*oscale);
                *(__half2*)(oh + (((size_t)(b1*HH + hh))*SS + s1)*DK + dd) =
                    __floats2half2_rn(v10*oscale, v11*oscale);
            } else {
                float* of = (float*)out;
                *(float2*)(of + (size_t)r0 * DM + c) = make_float2(v00, v01);
                *(float2*)(of + (size_t)r1 * DM + c) = make_float2(v10, v11);
            }
        }
    }
}

// ---------------------------------------------------------------------------
// Flash attention, fp16 mma + ldmatrix. One CTA per (b, h, 128-query tile).
// 256 thr = 8 warps, warp tile 16(q) x 64(k), warp-local softmax (fp32).
// Smem rows: 64 halves = 128B, XOR-swizzled 16B chunks (c ^ (row&7)).
// Staggered cp.async (R13 pipeline): V[it] under QK, K[it+1] under softmax+PV.
// ---------------------------------------------------------------------------
#define QT 128
#define KT 64
#define NIT (SS/KT)   // 32
#define Q_OFF 0
#define K_OFF (128*128)            // 16384
#define V_OFF (K_OFF + 64*128)     // 24576
#define P_OFF (V_OFF + 64*128)     // 32768
#define SM_TOT (P_OFF + 128*128)   // 49152
__global__ __launch_bounds__(256, 2) void attn_f16(const int* __restrict__ mask,
                                                   float* __restrict__ X)
{
    extern __shared__ char smb[];
    const unsigned su = (unsigned)__cvta_generic_to_shared(smb);

    const int tid = threadIdx.x, lane = tid & 31, wid = tid >> 5;
    const int g = lane >> 2, tg = lane & 3;
    const int wq = wid * 16;
    const int q0 = blockIdx.x * QT, h = blockIdx.y, b = blockIdx.z;
    const size_t hoff = ((size_t)(b*HH + h)) * SS * DK;

    // K/V loader: thread -> rows (tid>>3) and (tid>>3)+32, chunk tid&7 (swizzled)
    const int lr = tid >> 3, lc = tid & 7;

    // Prologue: K0 in flight while Q tile is staged
    #pragma unroll
    for (int j = 0; j < 2; j++) {
        int r = lr + j*32;
        cp16(smb + K_OFF + r*128 + ((lc ^ (r&7))<<4), g_K + hoff + (size_t)r*DK + lc*8);
    }
    asm volatile("cp.async.commit_group;" ::: "memory");

    // Q tile: 128 rows x 128B (already scaled by 1/8 at projection time)
    #pragma unroll
    for (int j = 0; j < 4; j++) {
        int r = lr + j*32;
        cp16(smb + Q_OFF + r*128 + ((lc ^ (r&7))<<4), g_Q + hoff + (size_t)(q0 + r)*DK + lc*8);
    }
    asm volatile("cp.async.commit_group;" ::: "memory");

    float o[8][4];
    #pragma unroll
    for (int nt = 0; nt < 8; nt++)
        #pragma unroll
        for (int i = 0; i < 4; i++) o[nt][i] = 0.f;
    float mprev0 = -INFINITY, mprev1 = -INFINITY, lsum0 = 0.f, lsum1 = 0.f;

    // ldmatrix address components (constant per thread)
    const int ar_row = wq + (lane & 7) + (lane & 8);        // A-frag rows (Q, P)
    const int ar_sw  = ar_row & 7;
    const int ar_ch  = (lane >> 4) & 1;                     // +8 halves for m2/m3
    const int mi = lane >> 3;

    #pragma unroll 1
    for (int it = 0; it < NIT; it++) {
        const int k0 = it * KT;

        asm volatile("cp.async.wait_group 0;" ::: "memory");  // K[it] (+Q on it=0)
        __syncthreads();   // sync#1: K visible; PV(it-1) done -> Vs free

        // issue V[it] (rides under mask LDG + QK)
        #pragma unroll
        for (int j = 0; j < 2; j++) {
            int r = lr + j*32;
            cp16(smb + V_OFF + r*128 + ((lc ^ (r&7))<<4),
                 g_V + hoff + (size_t)(k0 + r)*DK + lc*8);
        }
        asm volatile("cp.async.commit_group;" ::: "memory");

        // mask prefetch (hides under QK MMAs)
        int2 mr0[8], mr1[8];
        {
            const int* mp0 = mask + ((size_t)b*SS + (q0 + wq + g))*SS + k0;
            const int* mp1 = mp0 + 8*SS;
            #pragma unroll
            for (int nt = 0; nt < 8; nt++) {
                mr0[nt] = *(const int2*)(mp0 + nt*8 + tg*2);
                mr1[nt] = *(const int2*)(mp1 + nt*8 + tg*2);
            }
        }

        // ---- S = Qs @ K^T : 16x64 per warp (fp16, k16 steps) ----
        float s[8][4];
        #pragma unroll
        for (int nt = 0; nt < 8; nt++)
            #pragma unroll
            for (int i = 0; i < 4; i++) s[nt][i] = 0.f;
        #pragma unroll
        for (int k4 = 0; k4 < 4; k4++) {
            unsigned a[4], bb[8][2];
            {
                int c = 2*k4 + ar_ch;
                ldsm4(a, su + Q_OFF + ar_row*128 + ((c ^ ar_sw)<<4));
            }
            #pragma unroll
            for (int p = 0; p < 4; p++) {
                unsigned t[4];
                int r = p*16 + ((mi>>1)<<3) + (lane & 7);
                int c = 2*k4 + (mi & 1);
                ldsm4(t, su + K_OFF + r*128 + ((c ^ (r&7))<<4));
                bb[2*p][0]=t[0]; bb[2*p][1]=t[1]; bb[2*p+1][0]=t[2]; bb[2*p+1][1]=t[3];
            }
            #pragma unroll
            for (int nt = 0; nt < 8; nt++) mma16(s[nt], a, bb[nt]);
        }

        // ---- apply mask ----
        #pragma unroll
        for (int nt = 0; nt < 8; nt++) {
            if (mr0[nt].x == 0) s[nt][0] = -1e9f;
            if (mr0[nt].y == 0) s[nt][1] = -1e9f;
            if (mr1[nt].x == 0) s[nt][2] = -1e9f;
            if (mr1[nt].y == 0) s[nt][3] = -1e9f;
        }

        asm volatile("cp.async.wait_group 0;" ::: "memory");  // V[it] arrived
        __syncthreads();   // sync#2: V visible; QK done -> Ks free

        // issue K[it+1] (rides under softmax + PV)
        if (it + 1 < NIT) {
            #pragma unroll
            for (int j = 0; j < 2; j++) {
                int r = lr + j*32;
                cp16(smb + K_OFF + r*128 + ((lc ^ (r&7))<<4),
                     g_K + hoff + (size_t)(k0 + KT + r)*DK + lc*8);
            }
            asm volatile("cp.async.commit_group;" ::: "memory");
        }

        // ---- warp-local online softmax (fp32) ----
        float fr0, fr1;
        {
            float mx0 = fmaxf(s[0][0], s[0][1]), mx1 = fmaxf(s[0][2], s[0][3]);
            #pragma unroll
            for (int nt = 1; nt < 8; nt++) {
                mx0 = fmaxf(mx0, fmaxf(s[nt][0], s[nt][1]));
                mx1 = fmaxf(mx1, fmaxf(s[nt][2], s[nt][3]));
            }
            mx0 = fmaxf(mx0, __shfl_xor_sync(0xffffffffu, mx0, 1));
            mx0 = fmaxf(mx0, __shfl_xor_sync(0xffffffffu, mx0, 2));
            mx1 = fmaxf(mx1, __shfl_xor_sync(0xffffffffu, mx1, 1));
            mx1 = fmaxf(mx1, __shfl_xor_sync(0xffffffffu, mx1, 2));
            float mn0 = fmaxf(mprev0, mx0), mn1 = fmaxf(mprev1, mx1);
            fr0 = __expf(mprev0 - mn0); fr1 = __expf(mprev1 - mn1);
            mprev0 = mn0; mprev1 = mn1;
            float ps0 = 0.f, ps1 = 0.f;
            #pragma unroll
            for (int nt = 0; nt < 8; nt++) {
                float p0 = __expf(s[nt][0] - mn0), p1 = __expf(s[nt][1] - mn0);
                float p2 = __expf(s[nt][2] - mn1), p3 = __expf(s[nt][3] - mn1);
                s[nt][0] = p0; s[nt][1] = p1; s[nt][2] = p2; s[nt][3] = p3;
                ps0 += p0 + p1; ps1 += p2 + p3;
            }
            ps0 += __shfl_xor_sync(0xffffffffu, ps0, 1);
            ps0 += __shfl_xor_sync(0xffffffffu, ps0, 2);
            ps1 += __shfl_xor_sync(0xffffffffu, ps1, 1);
            ps1 += __shfl_xor_sync(0xffffffffu, ps1, 2);
            lsum0 = lsum0*fr0 + ps0;
            lsum1 = lsum1*fr1 + ps1;
        }

        // ---- spill P as fp16 (c-frag (g,2tg) pairs pack directly) ----
        {
            int r0 = wq + g, r1 = r0 + 8;
            #pragma unroll
            for (int nt = 0; nt < 8; nt++) {
                *(__half2*)(smb + P_OFF + r0*128 + ((nt ^ (r0&7))<<4) + tg*4) =
                    __floats2half2_rn(s[nt][0], s[nt][1]);
                *(__half2*)(smb + P_OFF + r1*128 + ((nt ^ (r1&7))<<4) + tg*4) =
                    __floats2half2_rn(s[nt][2], s[nt][3]);
            }
        }
        __syncwarp();

        // ---- rescale O, O += P @ V (V via ldmatrix.trans) ----
        #pragma unroll
        for (int nt = 0; nt < 8; nt++) {
            o[nt][0] *= fr0; o[nt][1] *= fr0;
            o[nt][2] *= fr1; o[nt][3] *= fr1;
        }
        #pragma unroll
        for (int k4 = 0; k4 < 4; k4++) {
            unsigned a[4], bb[8][2];
            {
                int c = 2*k4 + ar_ch;
                ldsm4(a, su + P_OFF + ar_row*128 + ((c ^ ar_sw)<<4));
            }
            #pragma unroll
            for (int p = 0; p < 4; p++) {
                unsigned t[4];
                int r = k4*16 + ((mi&1)<<3) + (lane & 7);   // V k-row
                int c = 2*p + (mi>>1);                       // d-chunk
                ldsm4t(t, su + V_OFF + r*128 + ((c ^ (r&7))<<4));
                bb[2*p][0]=t[0]; bb[2*p][1]=t[1]; bb[2*p+1][0]=t[2]; bb[2*p+1][1]=t[3];
            }
            #pragma unroll
            for (int nt = 0; nt < 8; nt++) mma16(o[nt], a, bb[nt]);
        }
    }

    // ---- normalize, write X fp32 [B,S,DM] (head-merged for Wo GEMM) ----
    {
        float i0 = 1.f / lsum0, i1 = 1.f / lsum1;
        float* x0 = X + ((size_t)b*SS + q0 + wq + g)*DM + h*DK;
        float* x1 = X + ((size_t)b*SS + q0 + wq + g + 8)*DM + h*DK;
        #pragma unroll
        for (int nt = 0; nt < 8; nt++) {
            *(float2*)(x0 + nt*8 + tg*2) = make_float2(o[nt][0]*i0, o[nt][1]*i0);
            *(float2*)(x1 + nt*8 + tg*2) = make_float2(o[nt][2]*i1, o[nt][3]*i1);
        }
    }
}

// ---------------------------------------------------------------------------
extern "C" void kernel_launch(void* const* d_in, const int* in_sizes, int n_in,
                              void* d_out, int out_size)
{
    const float* query = (const float*)d_in[0];
    const float* key   = (const float*)d_in[1];
    const float* value = (const float*)d_in[2];
    const int*   mask  = (const int*)  d_in[3];
    const float* Wq = (const float*)d_in[4];
    const float* bq = (const float*)d_in[5];
    const float* Wk = (const float*)d_in[6];
    const float* bk = (const float*)d_in[7];
    const float* Wv = (const float*)d_in[8];
    const float* bv = (const float*)d_in[9];
    const float* Wo = (const float*)d_in[10];
    const float* bo = (const float*)d_in[11];
    float* out = (float*)d_out;

    void *qp, *kp, *vp, *xp;
    cudaGetSymbolAddress(&qp, g_Q);
    cudaGetSymbolAddress(&kp, g_K);
    cudaGetSymbolAddress(&vp, g_V);
    cudaGetSymbolAddress(&xp, g_X);

    dim3 gg(DM/64, MTOT/128);   // (8, 64)
    gemm_tf32<<<gg, 256>>>(query, Wq, bq, qp, 1, 0.125f);   // Q pre-scaled
    gemm_tf32<<<gg, 256>>>(key,   Wk, bk, kp, 1, 1.0f);
    gemm_tf32<<<gg, 256>>>(value, Wv, bv, vp, 1, 1.0f);

    cudaFuncSetAttribute(attn_f16, cudaFuncAttributeMaxDynamicSharedMemorySize, SM_TOT);
    dim3 ag(SS/QT, HH, BB);     // (16, 8, 4)
    attn_f16<<<ag, 256, SM_TOT>>>(mask, (float*)xp);

    gemm_tf32<<<gg, 256>>>((const float*)xp, Wo, bo, d_out, 0, 1.0f);
}

// round 16
// speedup vs baseline: 2.2043x; 1.2487x over previous
#include <cuda_runtime.h>
#include <cuda_fp16.h>
#include <math.h>

#define BB 4
#define SS 2048
#define HH 8
#define DK 64
#define DM 512
#define MTOT (BB*SS)   // 8192

// Scratch (allocation-free rule: __device__ globals). Q/K/V fp16 (Q pre-scaled).
__device__ __half g_Q[BB*HH*SS*DK];
__device__ __half g_K[BB*HH*SS*DK];
__device__ __half g_V[BB*HH*SS*DK];
__device__ float  g_X[BB*SS*DM];

// ---------------------------------------------------------------------------
// Helpers. Lane = g*4+tg (g=lane>>2, tg=lane&3).
// fp16 m16n8k16, fp32 accumulate, everywhere.
// ---------------------------------------------------------------------------
__device__ __forceinline__ void mma16(float* d, const unsigned* a, const unsigned* b) {
    asm volatile("mma.sync.aligned.m16n8k16.row.col.f32.f16.f16.f32 "
        "{%0,%1,%2,%3},{%4,%5,%6,%7},{%8,%9},{%0,%1,%2,%3};"
        : "+f"(d[0]), "+f"(d[1]), "+f"(d[2]), "+f"(d[3])
        : "r"(a[0]), "r"(a[1]), "r"(a[2]), "r"(a[3]), "r"(b[0]), "r"(b[1]));
}
__device__ __forceinline__ void ldsm4(unsigned* r, unsigned addr) {
    asm volatile("ldmatrix.sync.aligned.m8n8.x4.shared.b16 {%0,%1,%2,%3}, [%4];"
        : "=r"(r[0]), "=r"(r[1]), "=r"(r[2]), "=r"(r[3]) : "r"(addr));
}
__device__ __forceinline__ void ldsm4t(unsigned* r, unsigned addr) {
    asm volatile("ldmatrix.sync.aligned.m8n8.x4.trans.shared.b16 {%0,%1,%2,%3}, [%4];"
        : "=r"(r[0]), "=r"(r[1]), "=r"(r[2]), "=r"(r[3]) : "r"(addr));
}
__device__ __forceinline__ void cp16(void* smem, const void* g) {
    unsigned saddr = (unsigned)__cvta_generic_to_shared(smem);
    asm volatile("cp.async.cg.shared.global [%0], [%1], 16;"
                 :: "r"(saddr), "l"(g) : "memory");
}
__device__ __forceinline__ unsigned packh2(float x, float y) {
    __half2 h = __floats2half2_rn(x, y);
    return *(unsigned*)&h;
}
__device__ __forceinline__ uint4 cvt8(float4 a, float4 b) {
    return make_uint4(packh2(a.x,a.y), packh2(a.z,a.w), packh2(b.x,b.y), packh2(b.z,b.w));
}

// ---------------------------------------------------------------------------
// GEMM: C[M,N] = A[M,512] @ W[N,512]^T + bias, fp16 mma (fp32 accum).
// Block 128m x 64n, 256 thr, warp grid 4m x 2n, warp tile 32x32, k-slab 32.
// Smem tiles as halves, 80B row stride (8 consecutive rows -> 8 distinct
// 16B banks: conflict-free LDSM with no swizzle).
// scatter=1: __half out to [B,H,S,DK], scaled. scatter=0: float [M,512].
// ---------------------------------------------------------------------------
#define AST 80
__global__ __launch_bounds__(256) void gemm_f16(
    const float* __restrict__ A, const float* __restrict__ W,
    const float* __restrict__ bias, void* __restrict__ out, int scatter, float oscale)
{
    __shared__ char Ah[128*AST];   // [m][32 halves]
    __shared__ char Wh[64*AST];    // [n][32 halves]
    const unsigned suA = (unsigned)__cvta_generic_to_shared(Ah);
    const unsigned suW = (unsigned)__cvta_generic_to_shared(Wh);

    const int tid = threadIdx.x, lane = tid & 31, wid = tid >> 5;
    const int g = lane >> 2, tg = lane & 3;
    const int wm = (wid & 3) * 32, wn = (wid >> 2) * 32;
    const int m0 = blockIdx.y * 128, n0 = blockIdx.x * 64;
    const int mi = lane >> 3;

    float acc[2][4][4];
    #pragma unroll
    for (int mt = 0; mt < 2; mt++)
        #pragma unroll
        for (int nt = 0; nt < 4; nt++)
            #pragma unroll
            for (int i = 0; i < 4; i++) acc[mt][nt][i] = 0.f;

    const int ar = tid >> 1, ah = tid & 1;     // A: row, 16-float half
    const int br = tid >> 2, bq = tid & 3;     // W: row, 8-float quarter
    const float* Abase = A + (size_t)(m0 + ar) * DM + ah*16;
    const float* Wbase = W + (size_t)(n0 + br) * DM + bq*8;

    float4 pva[4], pvw[2];
    #pragma unroll
    for (int i = 0; i < 4; i++) pva[i] = *(const float4*)(Abase + i*4);
    #pragma unroll
    for (int i = 0; i < 2; i++) pvw[i] = *(const float4*)(Wbase + i*4);

    const int a_row = wm + (lane & 7) + (lane & 8);
    const int a_ch  = (lane >> 4) & 1;

    for (int k0 = 0; k0 < DM; k0 += 32) {
        *(uint4*)(Ah + ar*AST + (ah*2+0)*16) = cvt8(pva[0], pva[1]);
        *(uint4*)(Ah + ar*AST + (ah*2+1)*16) = cvt8(pva[2], pva[3]);
        *(uint4*)(Wh + br*AST + bq*16)       = cvt8(pvw[0], pvw[1]);
        __syncthreads();

        if (k0 + 32 < DM) {
            #pragma unroll
            for (int i = 0; i < 4; i++) pva[i] = *(const float4*)(Abase + k0+32 + i*4);
            #pragma unroll
            for (int i = 0; i < 2; i++) pvw[i] = *(const float4*)(Wbase + k0+32 + i*4);
        }

        #pragma unroll
        for (int ks = 0; ks < 2; ks++) {
            unsigned a[2][4], b[4][2];
            #pragma unroll
            for (int mt = 0; mt < 2; mt++)
                ldsm4(a[mt], suA + (a_row + mt*16)*AST + (ks*2 + a_ch)*16);
            #pragma unroll
            for (int p = 0; p < 2; p++) {
                unsigned t[4];
                int r = wn + p*16 + ((mi>>1)<<3) + (lane & 7);
                ldsm4(t, suW + r*AST + (ks*2 + (mi&1))*16);
                b[2*p][0]=t[0]; b[2*p][1]=t[1]; b[2*p+1][0]=t[2]; b[2*p+1][1]=t[3];
            }
            #pragma unroll
            for (int mt = 0; mt < 2; mt++)
                #pragma unroll
                for (int nt = 0; nt < 4; nt++)
                    mma16(acc[mt][nt], a[mt], b[nt]);
        }
        __syncthreads();
    }

    #pragma unroll
    for (int mt = 0; mt < 2; mt++) {
        int r0 = m0 + wm + mt*16 + g;
        int r1 = r0 + 8;
        #pragma unroll
        for (int nt = 0; nt < 4; nt++) {
            int c = n0 + wn + nt*8 + tg*2;
            float2 bv = *(const float2*)(bias + c);
            float v00 = acc[mt][nt][0] + bv.x, v01 = acc[mt][nt][1] + bv.y;
            float v10 = acc[mt][nt][2] + bv.x, v11 = acc[mt][nt][3] + bv.y;
            if (scatter) {
                __half* oh = (__half*)out;
                int hh = c >> 6, dd = c & 63;
                int b0 = r0 >> 11, s0 = r0 & (SS-1);
                int b1 = r1 >> 11, s1 = r1 & (SS-1);
                *(__half2*)(oh + (((size_t)(b0*HH + hh))*SS + s0)*DK + dd) =
                    __floats2half2_rn(v00*oscale, v01*oscale);
                *(__half2*)(oh + (((size_t)(b1*HH + hh))*SS + s1)*DK + dd) =
                    __floats2half2_rn(v10*oscale, v11*oscale);
            } else {
                float* of = (float*)out;
                *(float2*)(of + (size_t)r0 * DM + c) = make_float2(v00, v01);
                *(float2*)(of + (size_t)r1 * DM + c) = make_float2(v10, v11);
            }
        }
    }
}

// ---------------------------------------------------------------------------
// Flash attention, fp16 mma + ldmatrix. One CTA per (b, h, 128-query tile).
// 256 thr = 8 warps, warp tile 16(q) x 64(k), warp-local softmax (fp32).
// P stays in registers: QK C-frags repack directly into PV A-frags (fp16 k16
// layouts coincide). Smem: Q 16K + K 8K + V 8K = 32KB, XOR-swizzled 128B rows.
// Staggered cp.async (R13 pipeline): V[it] under QK, K[it+1] under softmax+PV.
// ---------------------------------------------------------------------------
#define QT 128
#define KT 64
#define NIT (SS/KT)   // 32
#define Q_OFF 0
#define K_OFF (128*128)            // 16384
#define V_OFF (K_OFF + 64*128)     // 24576
#define SM_TOT (V_OFF + 64*128)    // 32768
__global__ __launch_bounds__(256, 2) void attn_f16(const int* __restrict__ mask,
                                                   float* __restrict__ X)
{
    extern __shared__ char smb[];
    const unsigned su = (unsigned)__cvta_generic_to_shared(smb);

    const int tid = threadIdx.x, lane = tid & 31, wid = tid >> 5;
    const int g = lane >> 2, tg = lane & 3;
    const int wq = wid * 16;
    const int q0 = blockIdx.x * QT, h = blockIdx.y, b = blockIdx.z;
    const size_t hoff = ((size_t)(b*HH + h)) * SS * DK;

    const int lr = tid >> 3, lc = tid & 7;

    // Prologue: K0 in flight while Q tile is staged
    #pragma unroll
    for (int j = 0; j < 2; j++) {
        int r = lr + j*32;
        cp16(smb + K_OFF + r*128 + ((lc ^ (r&7))<<4), g_K + hoff + (size_t)r*DK + lc*8);
    }
    asm volatile("cp.async.commit_group;" ::: "memory");

    #pragma unroll
    for (int j = 0; j < 4; j++) {
        int r = lr + j*32;
        cp16(smb + Q_OFF + r*128 + ((lc ^ (r&7))<<4), g_Q + hoff + (size_t)(q0 + r)*DK + lc*8);
    }
    asm volatile("cp.async.commit_group;" ::: "memory");

    float o[8][4];
    #pragma unroll
    for (int nt = 0; nt < 8; nt++)
        #pragma unroll
        for (int i = 0; i < 4; i++) o[nt][i] = 0.f;
    float mprev0 = -INFINITY, mprev1 = -INFINITY, lsum0 = 0.f, lsum1 = 0.f;

    const int ar_row = wq + (lane & 7) + (lane & 8);   // Q A-frag rows
    const int ar_sw  = ar_row & 7;
    const int ar_ch  = (lane >> 4) & 1;
    const int mi = lane >> 3;

    #pragma unroll 1
    for (int it = 0; it < NIT; it++) {
        const int k0 = it * KT;

        asm volatile("cp.async.wait_group 0;" ::: "memory");  // K[it] (+Q on it=0)
        __syncthreads();   // sync#1: K visible; PV(it-1) done -> Vs free

        // issue V[it] (rides under mask LDG + QK)
        #pragma unroll
        for (int j = 0; j < 2; j++) {
            int r = lr + j*32;
            cp16(smb + V_OFF + r*128 + ((lc ^ (r&7))<<4),
                 g_V + hoff + (size_t)(k0 + r)*DK + lc*8);
        }
        asm volatile("cp.async.commit_group;" ::: "memory");

        // mask prefetch (hides under QK MMAs)
        int2 mr0[8], mr1[8];
        {
            const int* mp0 = mask + ((size_t)b*SS + (q0 + wq + g))*SS + k0;
            const int* mp1 = mp0 + 8*SS;
            #pragma unroll
            for (int nt = 0; nt < 8; nt++) {
                mr0[nt] = *(const int2*)(mp0 + nt*8 + tg*2);
                mr1[nt] = *(const int2*)(mp1 + nt*8 + tg*2);
            }
        }

        // ---- S = Qs @ K^T : 16x64 per warp ----
        float s[8][4];
        #pragma unroll
        for (int nt = 0; nt < 8; nt++)
            #pragma unroll
            for (int i = 0; i < 4; i++) s[nt][i] = 0.f;
        #pragma unroll
        for (int k4 = 0; k4 < 4; k4++) {
            unsigned a[4], bb[8][2];
            {
                int c = 2*k4 + ar_ch;
                ldsm4(a, su + Q_OFF + ar_row*128 + ((c ^ ar_sw)<<4));
            }
            #pragma unroll
            for (int p = 0; p < 4; p++) {
                unsigned t[4];
                int r = p*16 + ((mi>>1)<<3) + (lane & 7);
                int c = 2*k4 + (mi & 1);
                ldsm4(t, su + K_OFF + r*128 + ((c ^ (r&7))<<4));
                bb[2*p][0]=t[0]; bb[2*p][1]=t[1]; bb[2*p+1][0]=t[2]; bb[2*p+1][1]=t[3];
            }
            #pragma unroll
            for (int nt = 0; nt < 8; nt++) mma16(s[nt], a, bb[nt]);
        }

        // ---- apply mask ----
        #pragma unroll
        for (int nt = 0; nt < 8; nt++) {
            if (mr0[nt].x == 0) s[nt][0] = -1e9f;
            if (mr0[nt].y == 0) s[nt][1] = -1e9f;
            if (mr1[nt].x == 0) s[nt][2] = -1e9f;
            if (mr1[nt].y == 0) s[nt][3] = -1e9f;
        }

        asm volatile("cp.async.wait_group 0;" ::: "memory");  // V[it] arrived
        __syncthreads();   // sync#2: V visible; QK done -> Ks free

        // issue K[it+1] (rides under softmax + PV)
        if (it + 1 < NIT) {
            #pragma unroll
            for (int j = 0; j < 2; j++) {
                int r = lr + j*32;
                cp16(smb + K_OFF + r*128 + ((lc ^ (r&7))<<4),
                     g_K + hoff + (size_t)(k0 + KT + r)*DK + lc*8);
            }
            asm volatile("cp.async.commit_group;" ::: "memory");
        }

        // ---- warp-local online softmax (fp32) ----
        float fr0, fr1;
        {
            float mx0 = fmaxf(s[0][0], s[0][1]), mx1 = fmaxf(s[0][2], s[0][3]);
            #pragma unroll
            for (int nt = 1; nt < 8; nt++) {
                mx0 = fmaxf(mx0, fmaxf(s[nt][0], s[nt][1]));
                mx1 = fmaxf(mx1, fmaxf(s[nt][2], s[nt][3]));
            }
            mx0 = fmaxf(mx0, __shfl_xor_sync(0xffffffffu, mx0, 1));
            mx0 = fmaxf(mx0, __shfl_xor_sync(0xffffffffu, mx0, 2));
            mx1 = fmaxf(mx1, __shfl_xor_sync(0xffffffffu, mx1, 1));
            mx1 = fmaxf(mx1, __shfl_xor_sync(0xffffffffu, mx1, 2));
            float mn0 = fmaxf(mprev0, mx0), mn1 = fmaxf(mprev1, mx1);
            fr0 = __expf(mprev0 - mn0); fr1 = __expf(mprev1 - mn1);
            mprev0 = mn0; mprev1 = mn1;
            float ps0 = 0.f, ps1 = 0.f;
            #pragma unroll
            for (int nt = 0; nt < 8; nt++) {
                float p0 = __expf(s[nt][0] - mn0), p1 = __expf(s[nt][1] - mn0);
                float p2 = __expf(s[nt][2] - mn1), p3 = __expf(s[nt][3] - mn1);
                s[nt][0] = p0; s[nt][1] = p1; s[nt][2] = p2; s[nt][3] = p3;
                ps0 += p0 + p1; ps1 += p2 + p3;
            }
            ps0 += __shfl_xor_sync(0xffffffffu, ps0, 1);
            ps0 += __shfl_xor_sync(0xffffffffu, ps0, 2);
            ps1 += __shfl_xor_sync(0xffffffffu, ps1, 1);
            ps1 += __shfl_xor_sync(0xffffffffu, ps1, 2);
            lsum0 = lsum0*fr0 + ps0;
            lsum1 = lsum1*fr1 + ps1;
        }

        // ---- rescale O; O += P @ V with P packed straight from registers ----
        // fp16 k16 A-frag (g, 2tg/2tg+1 | g+8) == QK C-frag layout: no smem.
        #pragma unroll
        for (int nt = 0; nt < 8; nt++) {
            o[nt][0] *= fr0; o[nt][1] *= fr0;
            o[nt][2] *= fr1; o[nt][3] *= fr1;
        }
        #pragma unroll
        for (int k4 = 0; k4 < 4; k4++) {
            unsigned a[4], bb[8][2];
            a[0] = packh2(s[2*k4][0],   s[2*k4][1]);
            a[1] = packh2(s[2*k4][2],   s[2*k4][3]);
            a[2] = packh2(s[2*k4+1][0], s[2*k4+1][1]);
            a[3] = packh2(s[2*k4+1][2], s[2*k4+1][3]);
            #pragma unroll
            for (int p = 0; p < 4; p++) {
                unsigned t[4];
                int r = k4*16 + ((mi&1)<<3) + (lane & 7);   // V k-row
                int c = 2*p + (mi>>1);                       // d-chunk
                ldsm4t(t, su + V_OFF + r*128 + ((c ^ (r&7))<<4));
                bb[2*p][0]=t[0]; bb[2*p][1]=t[1]; bb[2*p+1][0]=t[2]; bb[2*p+1][1]=t[3];
            }
            #pragma unroll
            for (int nt = 0; nt < 8; nt++) mma16(o[nt], a, bb[nt]);
        }
    }

    // ---- normalize, write X fp32 [B,S,DM] (head-merged for Wo GEMM) ----
    {
        float i0 = 1.f / lsum0, i1 = 1.f / lsum1;
        float* x0 = X + ((size_t)b*SS + q0 + wq + g)*DM + h*DK;
        float* x1 = X + ((size_t)b*SS + q0 + wq + g + 8)*DM + h*DK;
        #pragma unroll
        for (int nt = 0; nt < 8; nt++) {
            *(float2*)(x0 + nt*8 + tg*2) = make_float2(o[nt][0]*i0, o[nt][1]*i0);
            *(float2*)(x1 + nt*8 + tg*2) = make_float2(o[nt][2]*i1, o[nt][3]*i1);
        }
    }
}

// ---------------------------------------------------------------------------
extern "C" void kernel_launch(void* const* d_in, const int* in_sizes, int n_in,
                              void* d_out, int out_size)
{
    const float* query = (const float*)d_in[0];
    const float* key   = (const float*)d_in[1];
    const float* value = (const float*)d_in[2];
    const int*   mask  = (const int*)  d_in[3];
    const float* Wq = (const float*)d_in[4];
    const float* bq = (const float*)d_in[5];
    const float* Wk = (const float*)d_in[6];
    const float* bk = (const float*)d_in[7];
    const float* Wv = (const float*)d_in[8];
    const float* bv = (const float*)d_in[9];
    const float* Wo = (const float*)d_in[10];
    const float* bo = (const float*)d_in[11];

    void *qp, *kp, *vp, *xp;
    cudaGetSymbolAddress(&qp, g_Q);
    cudaGetSymbolAddress(&kp, g_K);
    cudaGetSymbolAddress(&vp, g_V);
    cudaGetSymbolAddress(&xp, g_X);

    dim3 gg(DM/64, MTOT/128);   // (8, 64)
    gemm_f16<<<gg, 256>>>(query, Wq, bq, qp, 1, 0.125f);   // Q pre-scaled by 1/8
    gemm_f16<<<gg, 256>>>(key,   Wk, bk, kp, 1, 1.0f);
    gemm_f16<<<gg, 256>>>(value, Wv, bv, vp, 1, 1.0f);

    cudaFuncSetAttribute(attn_f16, cudaFuncAttributeMaxDynamicSharedMemorySize, SM_TOT);
    dim3 ag(SS/QT, HH, BB);     // (16, 8, 4)
    attn_f16<<<ag, 256, SM_TOT>>>(mask, (float*)xp);

    gemm_f16<<<gg, 256>>>((const float*)xp, Wo, bo, d_out, 0, 1.0f);
}

// round 17
// speedup vs baseline: 2.2913x; 1.0395x over previous
#include <cuda_runtime.h>
#include <cuda_fp16.h>
#include <math.h>

#define BB 4
#define SS 2048
#define HH 8
#define DK 64
#define DM 512
#define MTOT (BB*SS)   // 8192

// Scratch (allocation-free rule: __device__ globals). Q/K/V fp16 (Q pre-scaled).
__device__ __half g_Q[BB*HH*SS*DK];
__device__ __half g_K[BB*HH*SS*DK];
__device__ __half g_V[BB*HH*SS*DK];
__device__ float  g_X[BB*SS*DM];

// ---------------------------------------------------------------------------
// Helpers. Lane = g*4+tg (g=lane>>2, tg=lane&3).
// fp16 m16n8k16, fp32 accumulate, everywhere.
// ---------------------------------------------------------------------------
__device__ __forceinline__ void mma16(float* d, const unsigned* a, const unsigned* b) {
    asm volatile("mma.sync.aligned.m16n8k16.row.col.f32.f16.f16.f32 "
        "{%0,%1,%2,%3},{%4,%5,%6,%7},{%8,%9},{%0,%1,%2,%3};"
        : "+f"(d[0]), "+f"(d[1]), "+f"(d[2]), "+f"(d[3])
        : "r"(a[0]), "r"(a[1]), "r"(a[2]), "r"(a[3]), "r"(b[0]), "r"(b[1]));
}
__device__ __forceinline__ void ldsm4(unsigned* r, unsigned addr) {
    asm volatile("ldmatrix.sync.aligned.m8n8.x4.shared.b16 {%0,%1,%2,%3}, [%4];"
        : "=r"(r[0]), "=r"(r[1]), "=r"(r[2]), "=r"(r[3]) : "r"(addr));
}
__device__ __forceinline__ void ldsm4t(unsigned* r, unsigned addr) {
    asm volatile("ldmatrix.sync.aligned.m8n8.x4.trans.shared.b16 {%0,%1,%2,%3}, [%4];"
        : "=r"(r[0]), "=r"(r[1]), "=r"(r[2]), "=r"(r[3]) : "r"(addr));
}
__device__ __forceinline__ void cp16(void* smem, const void* g) {
    unsigned saddr = (unsigned)__cvta_generic_to_shared(smem);
    asm volatile("cp.async.cg.shared.global [%0], [%1], 16;"
                 :: "r"(saddr), "l"(g) : "memory");
}
__device__ __forceinline__ unsigned packh2(float x, float y) {
    __half2 h = __floats2half2_rn(x, y);
    return *(unsigned*)&h;
}
__device__ __forceinline__ uint4 cvt8(float4 a, float4 b) {
    return make_uint4(packh2(a.x,a.y), packh2(a.z,a.w), packh2(b.x,b.y), packh2(b.z,b.w));
}

// ---------------------------------------------------------------------------
// GEMM: C[M,N] = A[M,512] @ W[N,512]^T + bias, fp16 mma (fp32 accum).
// (unchanged from R16 — measured ~43us each)
// ---------------------------------------------------------------------------
#define AST 80
__global__ __launch_bounds__(256) void gemm_f16(
    const float* __restrict__ A, const float* __restrict__ W,
    const float* __restrict__ bias, void* __restrict__ out, int scatter, float oscale)
{
    __shared__ char Ah[128*AST];   // [m][32 halves]
    __shared__ char Wh[64*AST];    // [n][32 halves]
    const unsigned suA = (unsigned)__cvta_generic_to_shared(Ah);
    const unsigned suW = (unsigned)__cvta_generic_to_shared(Wh);

    const int tid = threadIdx.x, lane = tid & 31, wid = tid >> 5;
    const int g = lane >> 2, tg = lane & 3;
    const int wm = (wid & 3) * 32, wn = (wid >> 2) * 32;
    const int m0 = blockIdx.y * 128, n0 = blockIdx.x * 64;
    const int mi = lane >> 3;

    float acc[2][4][4];
    #pragma unroll
    for (int mt = 0; mt < 2; mt++)
        #pragma unroll
        for (int nt = 0; nt < 4; nt++)
            #pragma unroll
            for (int i = 0; i < 4; i++) acc[mt][nt][i] = 0.f;

    const int ar = tid >> 1, ah = tid & 1;
    const int br = tid >> 2, bq = tid & 3;
    const float* Abase = A + (size_t)(m0 + ar) * DM + ah*16;
    const float* Wbase = W + (size_t)(n0 + br) * DM + bq*8;

    float4 pva[4], pvw[2];
    #pragma unroll
    for (int i = 0; i < 4; i++) pva[i] = *(const float4*)(Abase + i*4);
    #pragma unroll
    for (int i = 0; i < 2; i++) pvw[i] = *(const float4*)(Wbase + i*4);

    const int a_row = wm + (lane & 7) + (lane & 8);
    const int a_ch  = (lane >> 4) & 1;

    for (int k0 = 0; k0 < DM; k0 += 32) {
        *(uint4*)(Ah + ar*AST + (ah*2+0)*16) = cvt8(pva[0], pva[1]);
        *(uint4*)(Ah + ar*AST + (ah*2+1)*16) = cvt8(pva[2], pva[3]);
        *(uint4*)(Wh + br*AST + bq*16)       = cvt8(pvw[0], pvw[1]);
        __syncthreads();

        if (k0 + 32 < DM) {
            #pragma unroll
            for (int i = 0; i < 4; i++) pva[i] = *(const float4*)(Abase + k0+32 + i*4);
            #pragma unroll
            for (int i = 0; i < 2; i++) pvw[i] = *(const float4*)(Wbase + k0+32 + i*4);
        }

        #pragma unroll
        for (int ks = 0; ks < 2; ks++) {
            unsigned a[2][4], b[4][2];
            #pragma unroll
            for (int mt = 0; mt < 2; mt++)
                ldsm4(a[mt], suA + (a_row + mt*16)*AST + (ks*2 + a_ch)*16);
            #pragma unroll
            for (int p = 0; p < 2; p++) {
                unsigned t[4];
                int r = wn + p*16 + ((mi>>1)<<3) + (lane & 7);
                ldsm4(t, suW + r*AST + (ks*2 + (mi&1))*16);
                b[2*p][0]=t[0]; b[2*p][1]=t[1]; b[2*p+1][0]=t[2]; b[2*p+1][1]=t[3];
            }
            #pragma unroll
            for (int mt = 0; mt < 2; mt++)
                #pragma unroll
                for (int nt = 0; nt < 4; nt++)
                    mma16(acc[mt][nt], a[mt], b[nt]);
        }
        __syncthreads();
    }

    #pragma unroll
    for (int mt = 0; mt < 2; mt++) {
        int r0 = m0 + wm + mt*16 + g;
        int r1 = r0 + 8;
        #pragma unroll
        for (int nt = 0; nt < 4; nt++) {
            int c = n0 + wn + nt*8 + tg*2;
            float2 bv = *(const float2*)(bias + c);
            float v00 = acc[mt][nt][0] + bv.x, v01 = acc[mt][nt][1] + bv.y;
            float v10 = acc[mt][nt][2] + bv.x, v11 = acc[mt][nt][3] + bv.y;
            if (scatter) {
                __half* oh = (__half*)out;
                int hh = c >> 6, dd = c & 63;
                int b0 = r0 >> 11, s0 = r0 & (SS-1);
                int b1 = r1 >> 11, s1 = r1 & (SS-1);
                *(__half2*)(oh + (((size_t)(b0*HH + hh))*SS + s0)*DK + dd) =
                    __floats2half2_rn(v00*oscale, v01*oscale);
                *(__half2*)(oh + (((size_t)(b1*HH + hh))*SS + s1)*DK + dd) =
                    __floats2half2_rn(v10*oscale, v11*oscale);
            } else {
                float* of = (float*)out;
                *(float2*)(of + (size_t)r0 * DM + c) = make_float2(v00, v01);
                *(float2*)(of + (size_t)r1 * DM + c) = make_float2(v10, v11);
            }
        }
    }
}

// ---------------------------------------------------------------------------
// Flash attention, fp16 mma + ldmatrix. One CTA per (b, h, 128-query tile).
// 128 thr = 4 warps, warp tile 32(q) x 64(k) (mt=2 m-tiles): K/V B-fragments
// loaded once per warp, amortized over 2x MMAs (halves CTA LDSM traffic).
// 255 regs/thread available at 128thr x 2 CTAs/SM. Warp-local softmax; P in
// registers. Smem 32KB XOR-swizzled. Staggered cp.async pipeline (R13).
// ---------------------------------------------------------------------------
#define QT 128
#define KT 64
#define NIT (SS/KT)   // 32
#define Q_OFF 0
#define K_OFF (128*128)            // 16384
#define V_OFF (K_OFF + 64*128)     // 24576
#define SM_TOT (V_OFF + 64*128)    // 32768
__global__ __launch_bounds__(128, 2) void attn_f16(const int* __restrict__ mask,
                                                   float* __restrict__ X)
{
    extern __shared__ char smb[];
    const unsigned su = (unsigned)__cvta_generic_to_shared(smb);

    const int tid = threadIdx.x, lane = tid & 31, wid = tid >> 5;
    const int g = lane >> 2, tg = lane & 3;
    const int wq = wid * 32;                     // warp's 32 q-rows
    const int q0 = blockIdx.x * QT, h = blockIdx.y, b = blockIdx.z;
    const size_t hoff = ((size_t)(b*HH + h)) * SS * DK;

    const int lr = tid >> 3, lc = tid & 7;       // loader: 16 rows x 8 chunks

    // Prologue: K0 in flight while Q tile is staged
    #pragma unroll
    for (int j = 0; j < 4; j++) {
        int r = lr + j*16;
        cp16(smb + K_OFF + r*128 + ((lc ^ (r&7))<<4), g_K + hoff + (size_t)r*DK + lc*8);
    }
    asm volatile("cp.async.commit_group;" ::: "memory");

    #pragma unroll
    for (int j = 0; j < 8; j++) {
        int r = lr + j*16;
        cp16(smb + Q_OFF + r*128 + ((lc ^ (r&7))<<4), g_Q + hoff + (size_t)(q0 + r)*DK + lc*8);
    }
    asm volatile("cp.async.commit_group;" ::: "memory");

    float o[2][8][4];
    #pragma unroll
    for (int mt = 0; mt < 2; mt++)
        #pragma unroll
        for (int nt = 0; nt < 8; nt++)
            #pragma unroll
            for (int i = 0; i < 4; i++) o[mt][nt][i] = 0.f;
    float mprev[2][2], lsum[2][2];
    #pragma unroll
    for (int mt = 0; mt < 2; mt++) {
        mprev[mt][0] = -INFINITY; mprev[mt][1] = -INFINITY;
        lsum[mt][0] = 0.f; lsum[mt][1] = 0.f;
    }

    const int ar_row = wq + (lane & 7) + (lane & 8);   // Q A-frag base rows
    const int ar_sw  = ar_row & 7;                     // (+16 doesn't change &7)
    const int ar_ch  = (lane >> 4) & 1;
    const int mi = lane >> 3;

    #pragma unroll 1
    for (int it = 0; it < NIT; it++) {
        const int k0 = it * KT;

        asm volatile("cp.async.wait_group 0;" ::: "memory");  // K[it] (+Q on it=0)
        __syncthreads();   // sync#1: K visible; PV(it-1) done -> Vs free

        // issue V[it] (rides under mask LDG + QK)
        #pragma unroll
        for (int j = 0; j < 4; j++) {
            int r = lr + j*16;
            cp16(smb + V_OFF + r*128 + ((lc ^ (r&7))<<4),
                 g_V + hoff + (size_t)(k0 + r)*DK + lc*8);
        }
        asm volatile("cp.async.commit_group;" ::: "memory");

        // mask prefetch for both m-tiles (hides under QK MMAs)
        int2 mr0[2][8], mr1[2][8];
        #pragma unroll
        for (int mt = 0; mt < 2; mt++) {
            const int* mp0 = mask + ((size_t)b*SS + (q0 + wq + mt*16 + g))*SS + k0;
            const int* mp1 = mp0 + 8*SS;
            #pragma unroll
            for (int nt = 0; nt < 8; nt++) {
                mr0[mt][nt] = *(const int2*)(mp0 + nt*8 + tg*2);
                mr1[mt][nt] = *(const int2*)(mp1 + nt*8 + tg*2);
            }
        }

        // ---- S = Qs @ K^T : 32x64 per warp, K frags shared across mt ----
        float s[2][8][4];
        #pragma unroll
        for (int mt = 0; mt < 2; mt++)
            #pragma unroll
            for (int nt = 0; nt < 8; nt++)
                #pragma unroll
                for (int i = 0; i < 4; i++) s[mt][nt][i] = 0.f;
        #pragma unroll
        for (int k4 = 0; k4 < 4; k4++) {
            unsigned a[2][4], bb[8][2];
            {
                int c = 2*k4 + ar_ch;
                ldsm4(a[0], su + Q_OFF + ar_row*128 + ((c ^ ar_sw)<<4));
                ldsm4(a[1], su + Q_OFF + (ar_row+16)*128 + ((c ^ ar_sw)<<4));
            }
            #pragma unroll
            for (int p = 0; p < 4; p++) {
                unsigned t[4];
                int r = p*16 + ((mi>>1)<<3) + (lane & 7);
                int c = 2*k4 + (mi & 1);
                ldsm4(t, su + K_OFF + r*128 + ((c ^ (r&7))<<4));
                bb[2*p][0]=t[0]; bb[2*p][1]=t[1]; bb[2*p+1][0]=t[2]; bb[2*p+1][1]=t[3];
            }
            #pragma unroll
            for (int mt = 0; mt < 2; mt++)
                #pragma unroll
                for (int nt = 0; nt < 8; nt++)
                    mma16(s[mt][nt], a[mt], bb[nt]);
        }

        // ---- apply mask ----
        #pragma unroll
        for (int mt = 0; mt < 2; mt++)
            #pragma unroll
            for (int nt = 0; nt < 8; nt++) {
                if (mr0[mt][nt].x == 0) s[mt][nt][0] = -1e9f;
                if (mr0[mt][nt].y == 0) s[mt][nt][1] = -1e9f;
                if (mr1[mt][nt].x == 0) s[mt][nt][2] = -1e9f;
                if (mr1[mt][nt].y == 0) s[mt][nt][3] = -1e9f;
            }

        asm volatile("cp.async.wait_group 0;" ::: "memory");  // V[it] arrived
        __syncthreads();   // sync#2: V visible; QK done -> Ks free

        // issue K[it+1] (rides under softmax + PV)
        if (it + 1 < NIT) {
            #pragma unroll
            for (int j = 0; j < 4; j++) {
                int r = lr + j*16;
                cp16(smb + K_OFF + r*128 + ((lc ^ (r&7))<<4),
                     g_K + hoff + (size_t)(k0 + KT + r)*DK + lc*8);
            }
            asm volatile("cp.async.commit_group;" ::: "memory");
        }

        // ---- warp-local online softmax per m-tile; pack P to fp16 regs ----
        unsigned ap[2][16];
        float fr[2][2];
        #pragma unroll
        for (int mt = 0; mt < 2; mt++) {
            float mx0 = fmaxf(s[mt][0][0], s[mt][0][1]);
            float mx1 = fmaxf(s[mt][0][2], s[mt][0][3]);
            #pragma unroll
            for (int nt = 1; nt < 8; nt++) {
                mx0 = fmaxf(mx0, fmaxf(s[mt][nt][0], s[mt][nt][1]));
                mx1 = fmaxf(mx1, fmaxf(s[mt][nt][2], s[mt][nt][3]));
            }
            mx0 = fmaxf(mx0, __shfl_xor_sync(0xffffffffu, mx0, 1));
            mx0 = fmaxf(mx0, __shfl_xor_sync(0xffffffffu, mx0, 2));
            mx1 = fmaxf(mx1, __shfl_xor_sync(0xffffffffu, mx1, 1));
            mx1 = fmaxf(mx1, __shfl_xor_sync(0xffffffffu, mx1, 2));
            float mn0 = fmaxf(mprev[mt][0], mx0), mn1 = fmaxf(mprev[mt][1], mx1);
            fr[mt][0] = __expf(mprev[mt][0] - mn0);
            fr[mt][1] = __expf(mprev[mt][1] - mn1);
            mprev[mt][0] = mn0; mprev[mt][1] = mn1;
            float ps0 = 0.f, ps1 = 0.f;
            #pragma unroll
            for (int nt = 0; nt < 8; nt++) {
                float p0 = __expf(s[mt][nt][0] - mn0), p1 = __expf(s[mt][nt][1] - mn0);
                float p2 = __expf(s[mt][nt][2] - mn1), p3 = __expf(s[mt][nt][3] - mn1);
                ps0 += p0 + p1; ps1 += p2 + p3;
                s[mt][nt][0] = p0; s[mt][nt][1] = p1;
                s[mt][nt][2] = p2; s[mt][nt][3] = p3;
            }
            ps0 += __shfl_xor_sync(0xffffffffu, ps0, 1);
            ps0 += __shfl_xor_sync(0xffffffffu, ps0, 2);
            ps1 += __shfl_xor_sync(0xffffffffu, ps1, 1);
            ps1 += __shfl_xor_sync(0xffffffffu, ps1, 2);
            lsum[mt][0] = lsum[mt][0]*fr[mt][0] + ps0;
            lsum[mt][1] = lsum[mt][1]*fr[mt][1] + ps1;
            // pack P (fp16 k16 A-frag layout == QK C-frag layout)
            #pragma unroll
            for (int k4 = 0; k4 < 4; k4++) {
                ap[mt][k4*4+0] = packh2(s[mt][2*k4][0],   s[mt][2*k4][1]);
                ap[mt][k4*4+1] = packh2(s[mt][2*k4][2],   s[mt][2*k4][3]);
                ap[mt][k4*4+2] = packh2(s[mt][2*k4+1][0], s[mt][2*k4+1][1]);
                ap[mt][k4*4+3] = packh2(s[mt][2*k4+1][2], s[mt][2*k4+1][3]);
            }
        }

        // ---- rescale O; O += P @ V, V frags shared across mt ----
        #pragma unroll
        for (int mt = 0; mt < 2; mt++)
            #pragma unroll
            for (int nt = 0; nt < 8; nt++) {
                o[mt][nt][0] *= fr[mt][0]; o[mt][nt][1] *= fr[mt][0];
                o[mt][nt][2] *= fr[mt][1]; o[mt][nt][3] *= fr[mt][1];
            }
        #pragma unroll
        for (int k4 = 0; k4 < 4; k4++) {
            unsigned bb[8][2];
            #pragma unroll
            for (int p = 0; p < 4; p++) {
                unsigned t[4];
                int r = k4*16 + ((mi&1)<<3) + (lane & 7);   // V k-row
                int c = 2*p + (mi>>1);                       // d-chunk
                ldsm4t(t, su + V_OFF + r*128 + ((c ^ (r&7))<<4));
                bb[2*p][0]=t[0]; bb[2*p][1]=t[1]; bb[2*p+1][0]=t[2]; bb[2*p+1][1]=t[3];
            }
            #pragma unroll
            for (int mt = 0; mt < 2; mt++)
                #pragma unroll
                for (int nt = 0; nt < 8; nt++)
                    mma16(o[mt][nt], &ap[mt][k4*4], bb[nt]);
        }
    }

    // ---- normalize, write X fp32 [B,S,DM] (head-merged for Wo GEMM) ----
    #pragma unroll
    for (int mt = 0; mt < 2; mt++) {
        float i0 = 1.f / lsum[mt][0], i1 = 1.f / lsum[mt][1];
        float* x0 = X + ((size_t)b*SS + q0 + wq + mt*16 + g)*DM + h*DK;
        float* x1 = x0 + 8*DM;
        #pragma unroll
        for (int nt = 0; nt < 8; nt++) {
            *(float2*)(x0 + nt*8 + tg*2) = make_float2(o[mt][nt][0]*i0, o[mt][nt][1]*i0);
            *(float2*)(x1 + nt*8 + tg*2) = make_float2(o[mt][nt][2]*i1, o[mt][nt][3]*i1);
        }
    }
}

// ---------------------------------------------------------------------------
extern "C" void kernel_launch(void* const* d_in, const int* in_sizes, int n_in,
                              void* d_out, int out_size)
{
    const float* query = (const float*)d_in[0];
    const float* key   = (const float*)d_in[1];
    const float* value = (const float*)d_in[2];
    const int*   mask  = (const int*)  d_in[3];
    const float* Wq = (const float*)d_in[4];
    const float* bq = (const float*)d_in[5];
    const float* Wk = (const float*)d_in[6];
    const float* bk = (const float*)d_in[7];
    const float* Wv = (const float*)d_in[8];
    const float* bv = (const float*)d_in[9];
    const float* Wo = (const float*)d_in[10];
    const float* bo = (const float*)d_in[11];

    void *qp, *kp, *vp, *xp;
    cudaGetSymbolAddress(&qp, g_Q);
    cudaGetSymbolAddress(&kp, g_K);
    cudaGetSymbolAddress(&vp, g_V);
    cudaGetSymbolAddress(&xp, g_X);

    dim3 gg(DM/64, MTOT/128);   // (8, 64)
    gemm_f16<<<gg, 256>>>(query, Wq, bq, qp, 1, 0.125f);   // Q pre-scaled by 1/8
    gemm_f16<<<gg, 256>>>(key,   Wk, bk, kp, 1, 1.0f);
    gemm_f16<<<gg, 256>>>(value, Wv, bv, vp, 1, 1.0f);

    cudaFuncSetAttribute(attn_f16, cudaFuncAttributeMaxDynamicSharedMemorySize, SM_TOT);
    dim3 ag(SS/QT, HH, BB);     // (16, 8, 4)
    attn_f16<<<ag, 128, SM_TOT>>>(mask, (float*)xp);

    gemm_f16<<<gg, 256>>>((const float*)xp, Wo, bo, d_out, 0, 1.0f);
}